// round 10
// baseline (speedup 1.0000x reference)
#include <cuda_runtime.h>
#include <cuda_fp16.h>
#include <cstdint>

#define N_SEND 12288
#define N_REC  49152
#define NE     196608
#define DD     256
#define MTOT   98304
#define NROWX  24576   // 2 * N_SEND

// ---------------- static device scratch ----------------
__device__ __half d_Y[(size_t)NROWX * DD];     // Y = x @ W1a   (fp16)
__device__ __half d_Yacc[(size_t)MTOT * DD];   // segsum(Y[idx_send]) per batch
__device__ __half d_AccG[(size_t)N_REC * DD];  // segsum(gelu(edge mlp))
__device__ __half d_Amid[(size_t)MTOT * DD];   // gelu(H) fp16
__device__ __half d_B1Y[DD * 512];             // W1a^T duplicated (hi|lo split-K)
__device__ __half d_Bg[DD * DD];               // (We2 @ Wl1[256:])^T
__device__ __half d_B2[DD * DD];               // Wl2^T
__device__ float  d_bc[DD];
__device__ int    d_offs[N_REC + 1];

// ---------------- gelu ----------------
__device__ __forceinline__ float gelu_mufu(float v) {
    float u = 0.7978845608028654f * fmaf(0.044715f * v, v * v, v);
    float t;
    asm("ex2.approx.f32 %0, %1;" : "=f"(t) : "f"(-2.8853900817779268f * u));
    float r;
    asm("rcp.approx.f32 %0, %1;" : "=f"(r) : "f"(1.0f + t));
    return v * r;
}
__device__ __forceinline__ float gelu_poly(float v) {
    float u = 0.7978845608028654f * fmaf(0.044715f * v, v * v, v);
    float u2 = u * u;
    float p = fmaf(u2, -0.008863235530f, 0.021869488536f);
    p = fmaf(u2, p, -0.053968253968f);
    p = fmaf(u2, p, 0.133333333333f);
    p = fmaf(u2, p, -0.333333333333f);
    float th = fmaf(u2 * u, p, u);
    float g = fmaf(0.5f * v, th, 0.5f * v);
    if (__builtin_expect(fabsf(u) > 0.65f, 0)) g = gelu_mufu(v);
    return g;
}
__device__ __forceinline__ void ldsm4(uint32_t* r, uint32_t addr) {
    asm volatile("ldmatrix.sync.aligned.m8n8.x4.shared.b16 {%0,%1,%2,%3}, [%4];"
                 : "=r"(r[0]), "=r"(r[1]), "=r"(r[2]), "=r"(r[3]) : "r"(addr));
}
__device__ __forceinline__ void mma16816(float* c, const uint32_t* a, const uint32_t* b) {
    asm volatile("mma.sync.aligned.m16n8k16.row.col.f32.f16.f16.f32 "
                 "{%0,%1,%2,%3}, {%4,%5,%6,%7}, {%8,%9}, {%0,%1,%2,%3};"
                 : "+f"(c[0]), "+f"(c[1]), "+f"(c[2]), "+f"(c[3])
                 : "r"(a[0]), "r"(a[1]), "r"(a[2]), "r"(a[3]), "r"(b[0]), "r"(b[1]));
}
#define CP_ASYNC16(s, g) asm volatile("cp.async.cg.shared.global [%0], [%1], 16;" :: "r"(s), "l"(g))
#define CP_COMMIT()      asm volatile("cp.async.commit_group;" ::: "memory")
#define CP_WAIT(n)       asm volatile("cp.async.wait_group %0;" :: "n"(n) : "memory")

// ---------------- merged prep: B1Y, Bg, bc, B2 in one launch ----------------
__global__ void prep_all(const float* __restrict__ Wl1,
                         const float* __restrict__ We2,
                         const float* __restrict__ be2,
                         const float* __restrict__ Wl2) {
    int n = threadIdx.x;
    int b = blockIdx.x;
    if (b < 512) {
        d_B1Y[(size_t)n * 512 + b] = __float2half_rn(Wl1[(b & 255) * DD + n]);
    } else if (b < 768) {
        int j = b - 512;
        float acc = 0.f;
        #pragma unroll 4
        for (int kk = 0; kk < 256; kk++)
            acc += We2[j * 256 + kk] * Wl1[(256 + kk) * DD + n];
        d_Bg[(size_t)n * DD + j] = __float2half_rn(acc);
    } else if (b == 768) {
        float acc = 0.f;
        #pragma unroll 4
        for (int kk = 0; kk < 256; kk++)
            acc += be2[kk] * Wl1[(256 + kk) * DD + n];
        d_bc[n] = acc;
    } else {
        int k = b - 769;
        d_B2[(size_t)n * DD + k] = __float2half_rn(Wl2[k * DD + n]);
    }
}

// ---------------- segment offsets ----------------
__global__ void seg_offs_kernel(const int* __restrict__ idx_rec) {
    int e = blockIdx.x * 256 + threadIdx.x;
    if (e >= NE) return;
    int cur = idx_rec[e];
    int nxt = (e + 1 < NE) ? idx_rec[e + 1] : N_REC;
    for (int r = cur + 1; r <= nxt; r++) d_offs[r] = e + 1;
    if (e == 0) {
        for (int r = 0; r <= cur; r++) d_offs[r] = 0;
    }
}

// ---------------- fused gather(Y) + edge-MLP + segment sum (2 streams) ----------------
__global__ __launch_bounds__(256) void edge_kernel(const float* __restrict__ edge_attr,
                            const int*  __restrict__ idx_send,
                            const float* __restrict__ We1,
                            const float* __restrict__ be1) {
    const int r = blockIdx.x;
    const int d = threadIdx.x;
    const int start = d_offs[r], end = d_offs[r + 1];
    const int mid = (start + end + 1) >> 1;
    const int nA = mid - start, nB = end - mid;      // nA >= nB

    const float w0 = We1[d], w1 = We1[256 + d], w2 = We1[512 + d], w3 = We1[768 + d];
    const float b0 = be1[d];
    const __half* Y0 = d_Y;
    const __half* Y1 = d_Y + (size_t)N_SEND * DD;
    const float4* ea4 = (const float4*)edge_attr;

    float aG = 0.f, a0 = 0.f, a1 = 0.f;
    int sA = 0, sB = 0;
    float4 eaA, eaB;
    if (nA > 0) { sA = idx_send[start]; eaA = ea4[start]; }
    if (nB > 0) { sB = idx_send[mid];   eaB = ea4[mid]; }

    for (int i = 0; i < nA; i++) {
        int sc = sA; float4 ec = eaA;
        if (i + 1 < nA) { sA = idx_send[start + i + 1]; eaA = ea4[start + i + 1]; }
        bool hasB = (i < nB);
        int sc2 = sB; float4 ec2 = eaB;
        if (hasB && i + 1 < nB) { sB = idx_send[mid + i + 1]; eaB = ea4[mid + i + 1]; }

        float t = b0 + ec.x * w0 + ec.y * w1 + ec.z * w2 + ec.w * w3;
        aG += gelu_poly(t);
        a0 += __half2float(Y0[(size_t)sc * DD + d]);
        a1 += __half2float(Y1[(size_t)sc * DD + d]);
        if (hasB) {
            float t2 = b0 + ec2.x * w0 + ec2.y * w1 + ec2.z * w2 + ec2.w * w3;
            aG += gelu_poly(t2);
            a0 += __half2float(Y0[(size_t)sc2 * DD + d]);
            a1 += __half2float(Y1[(size_t)sc2 * DD + d]);
        }
    }
    d_Yacc[(size_t)r * DD + d]           = __float2half_rn(a0);
    d_Yacc[((size_t)N_REC + r) * DD + d] = __float2half_rn(a1);
    d_AccG[(size_t)r * DD + d]           = __float2half_rn(aG);
}

// ---------------- gemm_y: Y = x @ W1a with in-kernel fp32->hi/lo split ----------------
// A: x fp32 tile 128x256 -> 8 smem chunks (hi c<4, lo c>=4), preloaded once.
// B: d_B1Y pipelined via cp.async.
#define YA_BUF  0u
#define YB_BUF  131072u
#define YBUF_SZ 16384u
#define SMEM_Y_TOTAL (131072 + 3 * 16384)

__global__ __launch_bounds__(256, 1) void gemm_y(const float* __restrict__ x) {
    extern __shared__ char smem[];
    const uint32_t sb = (uint32_t)__cvta_generic_to_shared(smem);
    const int tid = threadIdx.x;
    const int tileN = blockIdx.x, tileM = blockIdx.y;
    const int wid = tid >> 5, lane = tid & 31;
    const int wm = (wid >> 2) * 64, wn = (wid & 3) * 32;

    const __half* Bg = d_B1Y;
    const size_t Bbase = (size_t)tileN * 128 * 512;

    // start B pipeline first (overlaps with A preload)
    #define LOADB(c, buf) do {                                               \
        uint32_t s_ = sb + YB_BUF + (uint32_t)(buf) * YBUF_SZ;               \
        _Pragma("unroll")                                                    \
        for (int i = 0; i < 4; i++) {                                        \
            int lin = i * 256 + tid;                                         \
            int rr_ = lin >> 3, cu_ = lin & 7;                               \
            uint32_t sa = s_ + (uint32_t)rr_ * 128u + (uint32_t)((cu_ ^ (rr_ & 7)) << 4); \
            CP_ASYNC16(sa, Bg + Bbase + (size_t)rr_ * 512 + (c) * 64 + cu_ * 8); \
        }                                                                    \
        CP_COMMIT();                                                         \
    } while (0)

    LOADB(0, 0); LOADB(1, 1); LOADB(2, 2);

    // A preload: 8 chunks (hi: c 0..3, lo: c 4..7), each 128 rows x 64 cols
    const float* xg = x + (size_t)tileM * 128 * DD;
    #pragma unroll
    for (int c = 0; c < 8; c++) {
        const int colbase = (c & 3) * 64;
        const bool lo = (c >= 4);
        char* abase = smem + YA_BUF + c * 16384;
        #pragma unroll
        for (int i = 0; i < 4; i++) {
            int lin = i * 256 + tid;
            int rr_ = lin >> 3, cu_ = lin & 7;
            const float4* gp = (const float4*)(xg + (size_t)rr_ * DD + colbase + cu_ * 8);
            float4 f0 = gp[0], f1 = gp[1];
            __half h[8];
            if (!lo) {
                h[0] = __float2half_rn(f0.x); h[1] = __float2half_rn(f0.y);
                h[2] = __float2half_rn(f0.z); h[3] = __float2half_rn(f0.w);
                h[4] = __float2half_rn(f1.x); h[5] = __float2half_rn(f1.y);
                h[6] = __float2half_rn(f1.z); h[7] = __float2half_rn(f1.w);
            } else {
                h[0] = __float2half_rn(f0.x - __half2float(__float2half_rn(f0.x)));
                h[1] = __float2half_rn(f0.y - __half2float(__float2half_rn(f0.y)));
                h[2] = __float2half_rn(f0.z - __half2float(__float2half_rn(f0.z)));
                h[3] = __float2half_rn(f0.w - __half2float(__float2half_rn(f0.w)));
                h[4] = __float2half_rn(f1.x - __half2float(__float2half_rn(f1.x)));
                h[5] = __float2half_rn(f1.y - __half2float(__float2half_rn(f1.y)));
                h[6] = __float2half_rn(f1.z - __half2float(__float2half_rn(f1.z)));
                h[7] = __float2half_rn(f1.w - __half2float(__float2half_rn(f1.w)));
            }
            *(uint4*)(abase + rr_ * 128 + ((cu_ ^ (rr_ & 7)) << 4)) = *(uint4*)h;
        }
    }
    __syncthreads();   // A ready

    const int sub = lane >> 3, rr8 = lane & 7;
    const int Ar0 = wm + ((sub & 1) << 3) + rr8;
    const int aSel = sub >> 1;
    const int Ar7 = Ar0 & 7;
    const int Bn0 = wn + ((sub >> 1) << 3) + rr8;
    const int bSel = sub & 1;
    const int Bn7 = Bn0 & 7;

    float acc[64];
    #pragma unroll
    for (int i = 0; i < 64; i++) acc[i] = 0.f;

    #pragma unroll
    for (int c = 0; c < 8; c++) {
        if (7 - c >= 2)      { CP_WAIT(2); }
        else if (7 - c == 1) { CP_WAIT(1); }
        else                 { CP_WAIT(0); }
        __syncthreads();
        const uint32_t sA = sb + YA_BUF + (uint32_t)c * 16384u;
        const uint32_t sB = sb + YB_BUF + (uint32_t)(c % 3) * YBUF_SZ;
        #pragma unroll
        for (int kk = 0; kk < 4; kk++) {
            uint32_t bh[8];
            #pragma unroll
            for (int p = 0; p < 2; p++) {
                int cB = kk * 2 + bSel;
                uint32_t boff = (uint32_t)(Bn0 + p * 16) * 128u + (uint32_t)((cB ^ Bn7) << 4);
                ldsm4(&bh[p * 4], sB + boff);
            }
            #pragma unroll
            for (int t = 0; t < 4; t++) {
                int cA = kk * 2 + aSel;
                uint32_t aoff = (uint32_t)(Ar0 + t * 16) * 128u + (uint32_t)((cA ^ Ar7) << 4);
                uint32_t ah[4];
                ldsm4(ah, sA + aoff);
                #pragma unroll
                for (int n = 0; n < 4; n++)
                    mma16816(&acc[(t * 4 + n) * 4], ah, &bh[(n >> 1) * 4 + (n & 1) * 2]);
            }
        }
        __syncthreads();
        if (c + 3 < 8) LOADB(c + 3, c % 3);
    }
    #undef LOADB

    const int gid = lane >> 2, qid = lane & 3;
    #pragma unroll
    for (int t = 0; t < 4; t++) {
        #pragma unroll
        for (int n = 0; n < 4; n++) {
            float* a4 = &acc[(t * 4 + n) * 4];
            size_t Rg = (size_t)tileM * 128 + wm + t * 16 + gid;
            int C = tileN * 128 + wn + n * 8 + qid * 2;
            *(__half2*)&d_Y[Rg * DD + C] = __floats2half2_rn(a4[0], a4[1]);
            *(__half2*)&d_Y[(Rg + 8) * DD + C] = __floats2half2_rn(a4[2], a4[3]);
        }
    }
}

// ---------------- HMMA GEMM (KD=256): MODE 3 = H->gelu->Amid; MODE 0 = final ----------------
#define SM_BIAS 0u
#define SM_BC   1024u
#define SM_CNT  2048u
#define SM_BUF  4096u
#define BUF_SZ  32768u
#define SMEM_TOTAL (4096 + 3 * 32768)

__device__ __forceinline__ void load_tile256(uint32_t sdst, const __half* __restrict__ g, int tid) {
    #pragma unroll
    for (int i = 0; i < 4; i++) {
        int lin = i * 256 + tid;
        int r = lin >> 3, c = lin & 7;
        uint32_t sa = sdst + (uint32_t)r * 128u + (uint32_t)((c ^ (r & 7)) << 4);
        CP_ASYNC16(sa, g + (size_t)r * 256 + c * 8);
    }
}

template <int MODE>
__global__ __launch_bounds__(256, 1) void gemm_hmma(const float* __restrict__ bias,
                                                    float* __restrict__ outp) {
    extern __shared__ char smem[];
    const uint32_t sb = (uint32_t)__cvta_generic_to_shared(smem);
    const int tid = threadIdx.x;
    const int tileN = blockIdx.x, tileM = blockIdx.y;
    const int wid = tid >> 5, lane = tid & 31;
    const int wm = (wid >> 2) * 64, wn = (wid & 3) * 32;

    const __half* Ag = (MODE == 3) ? d_AccG : d_Amid;
    const __half* Bg = (MODE == 3) ? d_Bg   : d_B2;

    if (tid < 128) {
        ((float*)(smem + SM_BIAS))[tid] = bias[tileN * 128 + tid];
        if (MODE == 3) {
            ((float*)(smem + SM_BC))[tid] = d_bc[tileN * 128 + tid];
            int R = tileM * 128 + tid;
            ((float*)(smem + SM_CNT))[tid] = (float)(d_offs[R + 1] - d_offs[R]);
        }
    }

    const size_t Abase = (size_t)tileM * 128 * 256;
    const size_t Bbase = (size_t)tileN * 128 * 256;

    #define LOAD_CHUNK(c, buf) do {                                         \
        uint32_t s_ = sb + SM_BUF + (uint32_t)(buf) * BUF_SZ;               \
        load_tile256(s_,          Ag + Abase + (c) * 64, tid);              \
        load_tile256(s_ + 16384u, Bg + Bbase + (c) * 64, tid);              \
        CP_COMMIT();                                                        \
    } while (0)

    LOAD_CHUNK(0, 0); LOAD_CHUNK(1, 1); LOAD_CHUNK(2, 2);

    const int sub = lane >> 3, rr8 = lane & 7;
    const int Ar0 = wm + ((sub & 1) << 3) + rr8;
    const int aSel = sub >> 1;
    const int Ar7 = Ar0 & 7;
    const int Bn0 = wn + ((sub >> 1) << 3) + rr8;
    const int bSel = sub & 1;
    const int Bn7 = Bn0 & 7;

    float acc[64];
    #pragma unroll
    for (int i = 0; i < 64; i++) acc[i] = 0.f;

    #pragma unroll
    for (int c = 0; c < 4; c++) {
        if (3 - c >= 2)      { CP_WAIT(2); }
        else if (3 - c == 1) { CP_WAIT(1); }
        else                 { CP_WAIT(0); }
        __syncthreads();

        const uint32_t sB0 = sb + SM_BUF + (uint32_t)(c % 3) * BUF_SZ;
        const uint32_t sA = sB0, sB = sB0 + 16384u;

        #pragma unroll
        for (int kk = 0; kk < 4; kk++) {
            uint32_t bh[8];
            #pragma unroll
            for (int p = 0; p < 2; p++) {
                int cB = kk * 2 + bSel;
                uint32_t boff = (uint32_t)(Bn0 + p * 16) * 128u + (uint32_t)((cB ^ Bn7) << 4);
                ldsm4(&bh[p * 4], sB + boff);
            }
            #pragma unroll
            for (int t = 0; t < 4; t++) {
                int cA = kk * 2 + aSel;
                uint32_t aoff = (uint32_t)(Ar0 + t * 16) * 128u + (uint32_t)((cA ^ Ar7) << 4);
                uint32_t ah[4];
                ldsm4(ah, sA + aoff);
                #pragma unroll
                for (int n = 0; n < 4; n++)
                    mma16816(&acc[(t * 4 + n) * 4], ah, &bh[(n >> 1) * 4 + (n & 1) * 2]);
            }
        }
        __syncthreads();
        if (c + 3 < 4) LOAD_CHUNK(c + 3, c % 3);
    }
    #undef LOAD_CHUNK

    const int gid = lane >> 2, qid = lane & 3;
    const float* sbias = (const float*)(smem + SM_BIAS);
    const float* sbc   = (const float*)(smem + SM_BC);
    const float* scnt  = (const float*)(smem + SM_CNT);

    #pragma unroll
    for (int t = 0; t < 4; t++) {
        #pragma unroll
        for (int n = 0; n < 4; n++) {
            float* a4 = &acc[(t * 4 + n) * 4];
            int rl = wm + t * 16 + gid;
            int cl = wn + n * 8 + qid * 2;
            size_t Rg = (size_t)tileM * 128 + rl;
            int C  = tileN * 128 + cl;
            if (MODE == 3) {
                float b0 = sbias[cl], b1 = sbias[cl + 1];
                float bc0 = sbc[cl], bc1 = sbc[cl + 1];
                float cf0 = scnt[rl], cf1 = scnt[rl + 8];
                float s00 = a4[0] + b0 + cf0 * bc0, s01 = a4[1] + b1 + cf0 * bc1;
                float s10 = a4[2] + b0 + cf1 * bc0, s11 = a4[3] + b1 + cf1 * bc1;
                __half2 y00 = *(const __half2*)&d_Yacc[Rg * DD + C];
                __half2 y01 = *(const __half2*)&d_Yacc[(Rg + 8) * DD + C];
                __half2 y10 = *(const __half2*)&d_Yacc[((size_t)N_REC + Rg) * DD + C];
                __half2 y11 = *(const __half2*)&d_Yacc[((size_t)N_REC + Rg + 8) * DD + C];
                *(__half2*)&d_Amid[Rg * DD + C] = __floats2half2_rn(
                    gelu_mufu(s00 + __low2float(y00)), gelu_mufu(s01 + __high2float(y00)));
                *(__half2*)&d_Amid[(Rg + 8) * DD + C] = __floats2half2_rn(
                    gelu_mufu(s10 + __low2float(y01)), gelu_mufu(s11 + __high2float(y01)));
                *(__half2*)&d_Amid[((size_t)N_REC + Rg) * DD + C] = __floats2half2_rn(
                    gelu_mufu(s00 + __low2float(y10)), gelu_mufu(s01 + __high2float(y10)));
                *(__half2*)&d_Amid[((size_t)N_REC + Rg + 8) * DD + C] = __floats2half2_rn(
                    gelu_mufu(s10 + __low2float(y11)), gelu_mufu(s11 + __high2float(y11)));
            } else {
                float b0 = sbias[cl], b1 = sbias[cl + 1];
                *(float2*)&outp[Rg * DD + C] = make_float2(a4[0] + b0, a4[1] + b1);
                *(float2*)&outp[(Rg + 8) * DD + C] = make_float2(a4[2] + b0, a4[3] + b1);
            }
        }
    }
}

// ---------------- launch ----------------
extern "C" void kernel_launch(void* const* d_in, const int* in_sizes, int n_in,
                              void* d_out, int out_size) {
    const float* x         = (const float*)d_in[0];
    const float* edge_attr = (const float*)d_in[1];
    const int*   idx_send  = (const int*)d_in[2];
    const int*   idx_rec   = (const int*)d_in[3];
    const float* We1       = (const float*)d_in[4];
    const float* be1       = (const float*)d_in[5];
    const float* We2       = (const float*)d_in[6];
    const float* be2       = (const float*)d_in[7];
    const float* Wl1       = (const float*)d_in[8];
    const float* bl1       = (const float*)d_in[9];
    const float* Wl2       = (const float*)d_in[10];
    const float* bl2       = (const float*)d_in[11];
    float* out = (float*)d_out;

    static bool attr_done = false;
    if (!attr_done) {
        cudaFuncSetAttribute(gemm_y, cudaFuncAttributeMaxDynamicSharedMemorySize, SMEM_Y_TOTAL);
        cudaFuncSetAttribute(gemm_hmma<3>, cudaFuncAttributeMaxDynamicSharedMemorySize, SMEM_TOTAL);
        cudaFuncSetAttribute(gemm_hmma<0>, cudaFuncAttributeMaxDynamicSharedMemorySize, SMEM_TOTAL);
        attr_done = true;
    }

    prep_all<<<1025, 256>>>(Wl1, We2, be2, Wl2);
    seg_offs_kernel<<<(NE + 255) / 256, 256>>>(idx_rec);
    gemm_y<<<dim3(2, NROWX / 128), 256, SMEM_Y_TOTAL>>>(x);                     // Y = x @ W1a
    edge_kernel<<<N_REC, 256>>>(edge_attr, idx_send, We1, be1);
    gemm_hmma<3><<<dim3(2, N_REC / 128), 256, SMEM_TOTAL>>>(bl1, nullptr);      // H -> gelu -> Amid
    gemm_hmma<0><<<dim3(2, MTOT / 128), 256, SMEM_TOTAL>>>(bl2, out);           // out
}

// round 11
// speedup vs baseline: 1.0800x; 1.0800x over previous
#include <cuda_runtime.h>
#include <cuda_fp16.h>
#include <cstdint>

#define N_SEND 12288
#define N_REC  49152
#define NE     196608
#define DD     256
#define MTOT   98304
#define NROWX  24576   // 2 * N_SEND

// ---------------- static device scratch ----------------
__device__ __half d_Y[(size_t)NROWX * DD];     // Y = x @ W1a   (fp16)
__device__ __half d_Yacc[(size_t)MTOT * DD];   // segsum(Y[idx_send]) per batch
__device__ __half d_AccG[(size_t)N_REC * DD];  // segsum(gelu(edge mlp))
__device__ __half d_Amid[(size_t)MTOT * DD];   // gelu(H) fp16
__device__ __half d_B1Y[DD * 512];             // W1a^T duplicated (hi|lo split-K)
__device__ __half d_Bg[DD * DD];               // (We2 @ Wl1[256:])^T
__device__ __half d_B2[DD * DD];               // Wl2^T
__device__ float  d_bc[DD];
__device__ int    d_offs[N_REC + 1];

// ---------------- gelu ----------------
__device__ __forceinline__ float gelu_mufu(float v) {
    float u = 0.7978845608028654f * fmaf(0.044715f * v, v * v, v);
    float t;
    asm("ex2.approx.f32 %0, %1;" : "=f"(t) : "f"(-2.8853900817779268f * u));
    float r;
    asm("rcp.approx.f32 %0, %1;" : "=f"(r) : "f"(1.0f + t));
    return v * r;
}
__device__ __forceinline__ float gelu_poly(float v) {
    float u = 0.7978845608028654f * fmaf(0.044715f * v, v * v, v);
    float u2 = u * u;
    float p = fmaf(u2, -0.008863235530f, 0.021869488536f);
    p = fmaf(u2, p, -0.053968253968f);
    p = fmaf(u2, p, 0.133333333333f);
    p = fmaf(u2, p, -0.333333333333f);
    float th = fmaf(u2 * u, p, u);
    float g = fmaf(0.5f * v, th, 0.5f * v);
    if (__builtin_expect(fabsf(u) > 0.65f, 0)) g = gelu_mufu(v);
    return g;
}
__device__ __forceinline__ void ldsm4(uint32_t* r, uint32_t addr) {
    asm volatile("ldmatrix.sync.aligned.m8n8.x4.shared.b16 {%0,%1,%2,%3}, [%4];"
                 : "=r"(r[0]), "=r"(r[1]), "=r"(r[2]), "=r"(r[3]) : "r"(addr));
}
__device__ __forceinline__ void mma16816(float* c, const uint32_t* a, const uint32_t* b) {
    asm volatile("mma.sync.aligned.m16n8k16.row.col.f32.f16.f16.f32 "
                 "{%0,%1,%2,%3}, {%4,%5,%6,%7}, {%8,%9}, {%0,%1,%2,%3};"
                 : "+f"(c[0]), "+f"(c[1]), "+f"(c[2]), "+f"(c[3])
                 : "r"(a[0]), "r"(a[1]), "r"(a[2]), "r"(a[3]), "r"(b[0]), "r"(b[1]));
}
#define CP_ASYNC16(s, g) asm volatile("cp.async.cg.shared.global [%0], [%1], 16;" :: "r"(s), "l"(g))
#define CP_COMMIT()      asm volatile("cp.async.commit_group;" ::: "memory")
#define CP_WAIT(n)       asm volatile("cp.async.wait_group %0;" :: "n"(n) : "memory")

// ---------------- merged prep: B1Y, Bg, bc, B2 in one launch ----------------
__global__ void prep_all(const float* __restrict__ Wl1,
                         const float* __restrict__ We2,
                         const float* __restrict__ be2,
                         const float* __restrict__ Wl2) {
    int n = threadIdx.x;
    int b = blockIdx.x;
    if (b < 512) {
        d_B1Y[(size_t)n * 512 + b] = __float2half_rn(Wl1[(b & 255) * DD + n]);
    } else if (b < 768) {
        int j = b - 512;
        float acc = 0.f;
        #pragma unroll 4
        for (int kk = 0; kk < 256; kk++)
            acc += We2[j * 256 + kk] * Wl1[(256 + kk) * DD + n];
        d_Bg[(size_t)n * DD + j] = __float2half_rn(acc);
    } else if (b == 768) {
        float acc = 0.f;
        #pragma unroll 4
        for (int kk = 0; kk < 256; kk++)
            acc += be2[kk] * Wl1[(256 + kk) * DD + n];
        d_bc[n] = acc;
    } else {
        int k = b - 769;
        d_B2[(size_t)n * DD + k] = __float2half_rn(Wl2[k * DD + n]);
    }
}

// ---------------- segment offsets ----------------
__global__ void seg_offs_kernel(const int* __restrict__ idx_rec) {
    int e = blockIdx.x * 256 + threadIdx.x;
    if (e >= NE) return;
    int cur = idx_rec[e];
    int nxt = (e + 1 < NE) ? idx_rec[e + 1] : N_REC;
    for (int r = cur + 1; r <= nxt; r++) d_offs[r] = e + 1;
    if (e == 0) {
        for (int r = 0; r <= cur; r++) d_offs[r] = 0;
    }
}

// ---------------- fused gather(Y) + edge-MLP + segment sum ----------------
// 256 threads = 2 segments x 128 threads; each thread owns a half2 (2 dims).
__global__ __launch_bounds__(256) void edge_kernel(const float* __restrict__ edge_attr,
                            const int*  __restrict__ idx_send,
                            const float* __restrict__ We1,
                            const float* __restrict__ be1) {
    const int r = blockIdx.x * 2 + (threadIdx.x >> 7);
    const int p = threadIdx.x & 127;          // half2 column
    const int start = d_offs[r], end = d_offs[r + 1];
    const int mid = (start + end + 1) >> 1;
    const int nA = mid - start, nB = end - mid;

    const float2 w0 = *(const float2*)&We1[2 * p];
    const float2 w1 = *(const float2*)&We1[256 + 2 * p];
    const float2 w2 = *(const float2*)&We1[512 + 2 * p];
    const float2 w3 = *(const float2*)&We1[768 + 2 * p];
    const float2 b0 = *(const float2*)&be1[2 * p];

    const __half2* __restrict__ Y2 = (const __half2*)d_Y;   // row stride 128
    const float4* __restrict__ ea4 = (const float4*)edge_attr;

    float2 aG = make_float2(0.f, 0.f), a0 = aG, a1 = aG;
    int sA = 0, sB = 0;
    float4 eaA, eaB;
    if (nA > 0) { sA = idx_send[start]; eaA = ea4[start]; }
    if (nB > 0) { sB = idx_send[mid];   eaB = ea4[mid]; }

    for (int i = 0; i < nA; i++) {
        int sc = sA; float4 ec = eaA;
        if (i + 1 < nA) { sA = idx_send[start + i + 1]; eaA = ea4[start + i + 1]; }
        bool hasB = (i < nB);
        int sc2 = sB; float4 ec2 = eaB;
        if (hasB && i + 1 < nB) { sB = idx_send[mid + i + 1]; eaB = ea4[mid + i + 1]; }

        {
            uint32_t off = (uint32_t)sc * 128u + (uint32_t)p;
            float tx = b0.x + ec.x * w0.x + ec.y * w1.x + ec.z * w2.x + ec.w * w3.x;
            float ty = b0.y + ec.x * w0.y + ec.y * w1.y + ec.z * w2.y + ec.w * w3.y;
            aG.x += gelu_poly(tx); aG.y += gelu_poly(ty);
            float2 y0 = __half22float2(Y2[off]);
            float2 y1 = __half22float2(Y2[off + (uint32_t)N_SEND * 128u]);
            a0.x += y0.x; a0.y += y0.y;
            a1.x += y1.x; a1.y += y1.y;
        }
        if (hasB) {
            uint32_t off = (uint32_t)sc2 * 128u + (uint32_t)p;
            float tx = b0.x + ec2.x * w0.x + ec2.y * w1.x + ec2.z * w2.x + ec2.w * w3.x;
            float ty = b0.y + ec2.x * w0.y + ec2.y * w1.y + ec2.z * w2.y + ec2.w * w3.y;
            aG.x += gelu_poly(tx); aG.y += gelu_poly(ty);
            float2 y0 = __half22float2(Y2[off]);
            float2 y1 = __half22float2(Y2[off + (uint32_t)N_SEND * 128u]);
            a0.x += y0.x; a0.y += y0.y;
            a1.x += y1.x; a1.y += y1.y;
        }
    }
    ((__half2*)d_Yacc)[(uint32_t)r * 128u + p]                          = __floats2half2_rn(a0.x, a0.y);
    ((__half2*)d_Yacc)[((uint32_t)N_REC + r) * 128u + p]                = __floats2half2_rn(a1.x, a1.y);
    ((__half2*)d_AccG)[(uint32_t)r * 128u + p]                          = __floats2half2_rn(aG.x, aG.y);
}

// ---------------- gemm_y: Y = x @ W1a with in-kernel fp32->hi/lo split ----------------
#define YA_BUF  0u
#define YB_BUF  131072u
#define YBUF_SZ 16384u
#define SMEM_Y_TOTAL (131072 + 3 * 16384)

__global__ __launch_bounds__(256, 1) void gemm_y(const float* __restrict__ x) {
    extern __shared__ char smem[];
    const uint32_t sb = (uint32_t)__cvta_generic_to_shared(smem);
    const int tid = threadIdx.x;
    const int tileN = blockIdx.x, tileM = blockIdx.y;
    const int wid = tid >> 5, lane = tid & 31;
    const int wm = (wid >> 2) * 64, wn = (wid & 3) * 32;

    const __half* Bg = d_B1Y;
    const size_t Bbase = (size_t)tileN * 128 * 512;

    #define LOADB(c, buf) do {                                               \
        uint32_t s_ = sb + YB_BUF + (uint32_t)(buf) * YBUF_SZ;               \
        _Pragma("unroll")                                                    \
        for (int i = 0; i < 4; i++) {                                        \
            int lin = i * 256 + tid;                                         \
            int rr_ = lin >> 3, cu_ = lin & 7;                               \
            uint32_t sa = s_ + (uint32_t)rr_ * 128u + (uint32_t)((cu_ ^ (rr_ & 7)) << 4); \
            CP_ASYNC16(sa, Bg + Bbase + (size_t)rr_ * 512 + (c) * 64 + cu_ * 8); \
        }                                                                    \
        CP_COMMIT();                                                         \
    } while (0)

    LOADB(0, 0); LOADB(1, 1); LOADB(2, 2);

    const float* xg = x + (size_t)tileM * 128 * DD;
    #pragma unroll
    for (int c = 0; c < 8; c++) {
        const int colbase = (c & 3) * 64;
        const bool lo = (c >= 4);
        char* abase = smem + YA_BUF + c * 16384;
        #pragma unroll
        for (int i = 0; i < 4; i++) {
            int lin = i * 256 + tid;
            int rr_ = lin >> 3, cu_ = lin & 7;
            const float4* gp = (const float4*)(xg + (size_t)rr_ * DD + colbase + cu_ * 8);
            float4 f0 = gp[0], f1 = gp[1];
            __half h[8];
            if (!lo) {
                h[0] = __float2half_rn(f0.x); h[1] = __float2half_rn(f0.y);
                h[2] = __float2half_rn(f0.z); h[3] = __float2half_rn(f0.w);
                h[4] = __float2half_rn(f1.x); h[5] = __float2half_rn(f1.y);
                h[6] = __float2half_rn(f1.z); h[7] = __float2half_rn(f1.w);
            } else {
                h[0] = __float2half_rn(f0.x - __half2float(__float2half_rn(f0.x)));
                h[1] = __float2half_rn(f0.y - __half2float(__float2half_rn(f0.y)));
                h[2] = __float2half_rn(f0.z - __half2float(__float2half_rn(f0.z)));
                h[3] = __float2half_rn(f0.w - __half2float(__float2half_rn(f0.w)));
                h[4] = __float2half_rn(f1.x - __half2float(__float2half_rn(f1.x)));
                h[5] = __float2half_rn(f1.y - __half2float(__float2half_rn(f1.y)));
                h[6] = __float2half_rn(f1.z - __half2float(__float2half_rn(f1.z)));
                h[7] = __float2half_rn(f1.w - __half2float(__float2half_rn(f1.w)));
            }
            *(uint4*)(abase + rr_ * 128 + ((cu_ ^ (rr_ & 7)) << 4)) = *(uint4*)h;
        }
    }
    __syncthreads();

    const int sub = lane >> 3, rr8 = lane & 7;
    const int Ar0 = wm + ((sub & 1) << 3) + rr8;
    const int aSel = sub >> 1;
    const int Ar7 = Ar0 & 7;
    const int Bn0 = wn + ((sub >> 1) << 3) + rr8;
    const int bSel = sub & 1;
    const int Bn7 = Bn0 & 7;

    float acc[64];
    #pragma unroll
    for (int i = 0; i < 64; i++) acc[i] = 0.f;

    #pragma unroll
    for (int c = 0; c < 8; c++) {
        if (7 - c >= 2)      { CP_WAIT(2); }
        else if (7 - c == 1) { CP_WAIT(1); }
        else                 { CP_WAIT(0); }
        __syncthreads();
        const uint32_t sA = sb + YA_BUF + (uint32_t)c * 16384u;
        const uint32_t sB = sb + YB_BUF + (uint32_t)(c % 3) * YBUF_SZ;
        #pragma unroll
        for (int kk = 0; kk < 4; kk++) {
            uint32_t bh[8];
            #pragma unroll
            for (int p = 0; p < 2; p++) {
                int cB = kk * 2 + bSel;
                uint32_t boff = (uint32_t)(Bn0 + p * 16) * 128u + (uint32_t)((cB ^ Bn7) << 4);
                ldsm4(&bh[p * 4], sB + boff);
            }
            #pragma unroll
            for (int t = 0; t < 4; t++) {
                int cA = kk * 2 + aSel;
                uint32_t aoff = (uint32_t)(Ar0 + t * 16) * 128u + (uint32_t)((cA ^ Ar7) << 4);
                uint32_t ah[4];
                ldsm4(ah, sA + aoff);
                #pragma unroll
                for (int n = 0; n < 4; n++)
                    mma16816(&acc[(t * 4 + n) * 4], ah, &bh[(n >> 1) * 4 + (n & 1) * 2]);
            }
        }
        __syncthreads();
        if (c + 3 < 8) LOADB(c + 3, c % 3);
    }
    #undef LOADB

    const int gid = lane >> 2, qid = lane & 3;
    #pragma unroll
    for (int t = 0; t < 4; t++) {
        #pragma unroll
        for (int n = 0; n < 4; n++) {
            float* a4 = &acc[(t * 4 + n) * 4];
            size_t Rg = (size_t)tileM * 128 + wm + t * 16 + gid;
            int C = tileN * 128 + wn + n * 8 + qid * 2;
            *(__half2*)&d_Y[Rg * DD + C] = __floats2half2_rn(a4[0], a4[1]);
            *(__half2*)&d_Y[(Rg + 8) * DD + C] = __floats2half2_rn(a4[2], a4[3]);
        }
    }
}

// ---------------- HMMA GEMM (KD=256): MODE 3 = H->gelu->Amid; MODE 0 = final ----------------
#define SM_BIAS 0u
#define SM_BC   1024u
#define SM_CNT  2048u
#define SM_BUF  4096u
#define BUF_SZ  32768u
#define SMEM_TOTAL (4096 + 3 * 32768)

__device__ __forceinline__ void load_tile256(uint32_t sdst, const __half* __restrict__ g, int tid) {
    #pragma unroll
    for (int i = 0; i < 4; i++) {
        int lin = i * 256 + tid;
        int r = lin >> 3, c = lin & 7;
        uint32_t sa = sdst + (uint32_t)r * 128u + (uint32_t)((c ^ (r & 7)) << 4);
        CP_ASYNC16(sa, g + (size_t)r * 256 + c * 8);
    }
}

template <int MODE>
__global__ __launch_bounds__(256, 1) void gemm_hmma(const float* __restrict__ bias,
                                                    float* __restrict__ outp) {
    extern __shared__ char smem[];
    const uint32_t sb = (uint32_t)__cvta_generic_to_shared(smem);
    const int tid = threadIdx.x;
    const int tileN = blockIdx.x, tileM = blockIdx.y;
    const int wid = tid >> 5, lane = tid & 31;
    const int wm = (wid >> 2) * 64, wn = (wid & 3) * 32;

    const __half* Ag = (MODE == 3) ? d_AccG : d_Amid;
    const __half* Bg = (MODE == 3) ? d_Bg   : d_B2;

    if (tid < 128) {
        ((float*)(smem + SM_BIAS))[tid] = bias[tileN * 128 + tid];
        if (MODE == 3) {
            ((float*)(smem + SM_BC))[tid] = d_bc[tileN * 128 + tid];
            int R = tileM * 128 + tid;
            ((float*)(smem + SM_CNT))[tid] = (float)(d_offs[R + 1] - d_offs[R]);
        }
    }

    const size_t Abase = (size_t)tileM * 128 * 256;
    const size_t Bbase = (size_t)tileN * 128 * 256;

    #define LOAD_CHUNK(c, buf) do {                                         \
        uint32_t s_ = sb + SM_BUF + (uint32_t)(buf) * BUF_SZ;               \
        load_tile256(s_,          Ag + Abase + (c) * 64, tid);              \
        load_tile256(s_ + 16384u, Bg + Bbase + (c) * 64, tid);              \
        CP_COMMIT();                                                        \
    } while (0)

    LOAD_CHUNK(0, 0); LOAD_CHUNK(1, 1); LOAD_CHUNK(2, 2);

    const int sub = lane >> 3, rr8 = lane & 7;
    const int Ar0 = wm + ((sub & 1) << 3) + rr8;
    const int aSel = sub >> 1;
    const int Ar7 = Ar0 & 7;
    const int Bn0 = wn + ((sub >> 1) << 3) + rr8;
    const int bSel = sub & 1;
    const int Bn7 = Bn0 & 7;

    float acc[64];
    #pragma unroll
    for (int i = 0; i < 64; i++) acc[i] = 0.f;

    #pragma unroll
    for (int c = 0; c < 4; c++) {
        if (3 - c >= 2)      { CP_WAIT(2); }
        else if (3 - c == 1) { CP_WAIT(1); }
        else                 { CP_WAIT(0); }
        __syncthreads();

        const uint32_t sB0 = sb + SM_BUF + (uint32_t)(c % 3) * BUF_SZ;
        const uint32_t sA = sB0, sB = sB0 + 16384u;

        #pragma unroll
        for (int kk = 0; kk < 4; kk++) {
            uint32_t bh[8];
            #pragma unroll
            for (int p = 0; p < 2; p++) {
                int cB = kk * 2 + bSel;
                uint32_t boff = (uint32_t)(Bn0 + p * 16) * 128u + (uint32_t)((cB ^ Bn7) << 4);
                ldsm4(&bh[p * 4], sB + boff);
            }
            #pragma unroll
            for (int t = 0; t < 4; t++) {
                int cA = kk * 2 + aSel;
                uint32_t aoff = (uint32_t)(Ar0 + t * 16) * 128u + (uint32_t)((cA ^ Ar7) << 4);
                uint32_t ah[4];
                ldsm4(ah, sA + aoff);
                #pragma unroll
                for (int n = 0; n < 4; n++)
                    mma16816(&acc[(t * 4 + n) * 4], ah, &bh[(n >> 1) * 4 + (n & 1) * 2]);
            }
        }
        __syncthreads();
        if (c + 3 < 4) LOAD_CHUNK(c + 3, c % 3);
    }
    #undef LOAD_CHUNK

    const int gid = lane >> 2, qid = lane & 3;
    const float* sbias = (const float*)(smem + SM_BIAS);
    const float* sbc   = (const float*)(smem + SM_BC);
    const float* scnt  = (const float*)(smem + SM_CNT);

    #pragma unroll
    for (int t = 0; t < 4; t++) {
        #pragma unroll
        for (int n = 0; n < 4; n++) {
            float* a4 = &acc[(t * 4 + n) * 4];
            int rl = wm + t * 16 + gid;
            int cl = wn + n * 8 + qid * 2;
            size_t Rg = (size_t)tileM * 128 + rl;
            int C  = tileN * 128 + cl;
            if (MODE == 3) {
                float b0 = sbias[cl], b1 = sbias[cl + 1];
                float bc0 = sbc[cl], bc1 = sbc[cl + 1];
                float cf0 = scnt[rl], cf1 = scnt[rl + 8];
                float s00 = a4[0] + b0 + cf0 * bc0, s01 = a4[1] + b1 + cf0 * bc1;
                float s10 = a4[2] + b0 + cf1 * bc0, s11 = a4[3] + b1 + cf1 * bc1;
                __half2 y00 = *(const __half2*)&d_Yacc[Rg * DD + C];
                __half2 y01 = *(const __half2*)&d_Yacc[(Rg + 8) * DD + C];
                __half2 y10 = *(const __half2*)&d_Yacc[((size_t)N_REC + Rg) * DD + C];
                __half2 y11 = *(const __half2*)&d_Yacc[((size_t)N_REC + Rg + 8) * DD + C];
                *(__half2*)&d_Amid[Rg * DD + C] = __floats2half2_rn(
                    gelu_mufu(s00 + __low2float(y00)), gelu_mufu(s01 + __high2float(y00)));
                *(__half2*)&d_Amid[(Rg + 8) * DD + C] = __floats2half2_rn(
                    gelu_mufu(s10 + __low2float(y01)), gelu_mufu(s11 + __high2float(y01)));
                *(__half2*)&d_Amid[((size_t)N_REC + Rg) * DD + C] = __floats2half2_rn(
                    gelu_mufu(s00 + __low2float(y10)), gelu_mufu(s01 + __high2float(y10)));
                *(__half2*)&d_Amid[((size_t)N_REC + Rg + 8) * DD + C] = __floats2half2_rn(
                    gelu_mufu(s10 + __low2float(y11)), gelu_mufu(s11 + __high2float(y11)));
            } else {
                float b0 = sbias[cl], b1 = sbias[cl + 1];
                *(float2*)&outp[Rg * DD + C] = make_float2(a4[0] + b0, a4[1] + b1);
                *(float2*)&outp[(Rg + 8) * DD + C] = make_float2(a4[2] + b0, a4[3] + b1);
            }
        }
    }
}

// ---------------- launch ----------------
extern "C" void kernel_launch(void* const* d_in, const int* in_sizes, int n_in,
                              void* d_out, int out_size) {
    const float* x         = (const float*)d_in[0];
    const float* edge_attr = (const float*)d_in[1];
    const int*   idx_send  = (const int*)d_in[2];
    const int*   idx_rec   = (const int*)d_in[3];
    const float* We1       = (const float*)d_in[4];
    const float* be1       = (const float*)d_in[5];
    const float* We2       = (const float*)d_in[6];
    const float* be2       = (const float*)d_in[7];
    const float* Wl1       = (const float*)d_in[8];
    const float* bl1       = (const float*)d_in[9];
    const float* Wl2       = (const float*)d_in[10];
    const float* bl2       = (const float*)d_in[11];
    float* out = (float*)d_out;

    static bool attr_done = false;
    if (!attr_done) {
        cudaFuncSetAttribute(gemm_y, cudaFuncAttributeMaxDynamicSharedMemorySize, SMEM_Y_TOTAL);
        cudaFuncSetAttribute(gemm_hmma<3>, cudaFuncAttributeMaxDynamicSharedMemorySize, SMEM_TOTAL);
        cudaFuncSetAttribute(gemm_hmma<0>, cudaFuncAttributeMaxDynamicSharedMemorySize, SMEM_TOTAL);
        attr_done = true;
    }

    prep_all<<<1025, 256>>>(Wl1, We2, be2, Wl2);
    seg_offs_kernel<<<(NE + 255) / 256, 256>>>(idx_rec);
    gemm_y<<<dim3(2, NROWX / 128), 256, SMEM_Y_TOTAL>>>(x);                     // Y = x @ W1a
    edge_kernel<<<N_REC / 2, 256>>>(edge_attr, idx_send, We1, be1);
    gemm_hmma<3><<<dim3(2, N_REC / 128), 256, SMEM_TOTAL>>>(bl1, nullptr);      // H -> gelu -> Amid
    gemm_hmma<0><<<dim3(2, MTOT / 128), 256, SMEM_TOTAL>>>(bl2, out);           // out
}

// round 12
// speedup vs baseline: 1.2219x; 1.1314x over previous
#include <cuda_runtime.h>
#include <cuda_fp16.h>
#include <cstdint>

#define N_SEND 12288
#define N_REC  49152
#define NE     196608
#define DD     256
#define MTOT   98304
#define NROWX  24576   // 2 * N_SEND

// ---------------- static device scratch ----------------
__device__ __half d_Y[(size_t)NROWX * DD];     // Y = x @ W1a   (fp16)
__device__ __half d_Yacc[(size_t)MTOT * DD];   // segsum(Y[idx_send]) per batch
__device__ __half d_AccG[(size_t)N_REC * DD];  // segsum(gelu(edge mlp))
__device__ __half d_Amid[(size_t)MTOT * DD];   // gelu(H) fp16
__device__ __half d_B1Y[DD * 512];             // W1a^T duplicated (hi|lo split-K)
__device__ __half d_Bg[DD * DD];               // (We2 @ Wl1[256:])^T
__device__ __half d_B2[DD * DD];               // Wl2^T
__device__ float  d_bc[DD];
__device__ int    d_offs[N_REC + 1];

// ---------------- gelu ----------------
__device__ __forceinline__ float gelu_mufu(float v) {
    float u = 0.7978845608028654f * fmaf(0.044715f * v, v * v, v);
    float t;
    asm("ex2.approx.f32 %0, %1;" : "=f"(t) : "f"(-2.8853900817779268f * u));
    float r;
    asm("rcp.approx.f32 %0, %1;" : "=f"(r) : "f"(1.0f + t));
    return v * r;
}
// packed fp16 gelu: deg-5 tanh poly (args here satisfy |u| < ~0.55; trunc err < fp16 ulp floor)
__device__ __forceinline__ __half2 gelu_h2(__half2 t) {
    const __half2 c_a = __float2half2_rn(0.044715f);
    const __half2 c_s = __float2half2_rn(0.7978845608f);
    const __half2 c3  = __float2half2_rn(-0.33333333f);
    const __half2 c5  = __float2half2_rn(0.13333333f);
    const __half2 h05 = __float2half2_rn(0.5f);
    __half2 t2 = __hmul2(t, t);
    __half2 inner = __hfma2(__hmul2(c_a, t), t2, t);
    __half2 u = __hmul2(c_s, inner);
    __half2 u2 = __hmul2(u, u);
    __half2 p = __hfma2(u2, c5, c3);
    __half2 th = __hfma2(__hmul2(u, u2), p, u);
    __half2 hh = __hfma2(th, h05, h05);
    return __hmul2(t, hh);
}
__device__ __forceinline__ void ldsm4(uint32_t* r, uint32_t addr) {
    asm volatile("ldmatrix.sync.aligned.m8n8.x4.shared.b16 {%0,%1,%2,%3}, [%4];"
                 : "=r"(r[0]), "=r"(r[1]), "=r"(r[2]), "=r"(r[3]) : "r"(addr));
}
__device__ __forceinline__ void mma16816(float* c, const uint32_t* a, const uint32_t* b) {
    asm volatile("mma.sync.aligned.m16n8k16.row.col.f32.f16.f16.f32 "
                 "{%0,%1,%2,%3}, {%4,%5,%6,%7}, {%8,%9}, {%0,%1,%2,%3};"
                 : "+f"(c[0]), "+f"(c[1]), "+f"(c[2]), "+f"(c[3])
                 : "r"(a[0]), "r"(a[1]), "r"(a[2]), "r"(a[3]), "r"(b[0]), "r"(b[1]));
}
#define CP_ASYNC16(s, g) asm volatile("cp.async.cg.shared.global [%0], [%1], 16;" :: "r"(s), "l"(g))
#define CP_COMMIT()      asm volatile("cp.async.commit_group;" ::: "memory")
#define CP_WAIT(n)       asm volatile("cp.async.wait_group %0;" :: "n"(n) : "memory")

// ---------------- merged prep: B1Y, Bg, bc, B2 in one launch ----------------
__global__ void prep_all(const float* __restrict__ Wl1,
                         const float* __restrict__ We2,
                         const float* __restrict__ be2,
                         const float* __restrict__ Wl2) {
    int n = threadIdx.x;
    int b = blockIdx.x;
    if (b < 512) {
        d_B1Y[(size_t)n * 512 + b] = __float2half_rn(Wl1[(b & 255) * DD + n]);
    } else if (b < 768) {
        int j = b - 512;
        float acc = 0.f;
        #pragma unroll 4
        for (int kk = 0; kk < 256; kk++)
            acc += We2[j * 256 + kk] * Wl1[(256 + kk) * DD + n];
        d_Bg[(size_t)n * DD + j] = __float2half_rn(acc);
    } else if (b == 768) {
        float acc = 0.f;
        #pragma unroll 4
        for (int kk = 0; kk < 256; kk++)
            acc += be2[kk] * Wl1[(256 + kk) * DD + n];
        d_bc[n] = acc;
    } else {
        int k = b - 769;
        d_B2[(size_t)n * DD + k] = __float2half_rn(Wl2[k * DD + n]);
    }
}

// ---------------- segment offsets ----------------
__global__ void seg_offs_kernel(const int* __restrict__ idx_rec) {
    int e = blockIdx.x * 256 + threadIdx.x;
    if (e >= NE) return;
    int cur = idx_rec[e];
    int nxt = (e + 1 < NE) ? idx_rec[e + 1] : N_REC;
    for (int r = cur + 1; r <= nxt; r++) d_offs[r] = e + 1;
    if (e == 0) {
        for (int r = 0; r <= cur; r++) d_offs[r] = 0;
    }
}

// ---------------- fused gather(Y) + edge-MLP + segment sum ----------------
// 256 threads = 4 segments x 64 threads; each thread owns 4 dims (one uint2 = 2 half2).
__global__ __launch_bounds__(256) void edge_kernel(const float* __restrict__ edge_attr,
                            const int*  __restrict__ idx_send,
                            const float* __restrict__ We1,
                            const float* __restrict__ be1) {
    const int r = blockIdx.x * 4 + (threadIdx.x >> 6);
    const int q = threadIdx.x & 63;            // owns dims [4q, 4q+4)
    const int start = d_offs[r], end = d_offs[r + 1];
    const int mid = (start + end + 1) >> 1;
    const int nA = mid - start, nB = end - mid;   // nA >= nB

    const float4 w0 = *(const float4*)&We1[4 * q];
    const float4 w1 = *(const float4*)&We1[256 + 4 * q];
    const float4 w2 = *(const float4*)&We1[512 + 4 * q];
    const float4 w3 = *(const float4*)&We1[768 + 4 * q];
    const float4 b0 = *(const float4*)&be1[4 * q];

    const uint2* __restrict__ Y4 = (const uint2*)d_Y;   // row stride = 64 uint2
    const float4* __restrict__ ea4 = (const float4*)edge_attr;

    float4 aG = make_float4(0.f, 0.f, 0.f, 0.f);
    float4 a0 = aG, a1 = aG;

    for (int i = 0; i < nA; i++) {
        {   // stream A
            const int e = start + i;
            const int s = idx_send[e];
            const float4 ea = ea4[e];
            float t0 = b0.x + ea.x * w0.x + ea.y * w1.x + ea.z * w2.x + ea.w * w3.x;
            float t1 = b0.y + ea.x * w0.y + ea.y * w1.y + ea.z * w2.y + ea.w * w3.y;
            float t2 = b0.z + ea.x * w0.z + ea.y * w1.z + ea.z * w2.z + ea.w * w3.z;
            float t3 = b0.w + ea.x * w0.w + ea.y * w1.w + ea.z * w2.w + ea.w * w3.w;
            float2 g01 = __half22float2(gelu_h2(__floats2half2_rn(t0, t1)));
            float2 g23 = __half22float2(gelu_h2(__floats2half2_rn(t2, t3)));
            aG.x += g01.x; aG.y += g01.y; aG.z += g23.x; aG.w += g23.y;
            uint32_t off = (uint32_t)s * 64u + (uint32_t)q;
            uint2 y0 = Y4[off];
            uint2 y1 = Y4[off + (uint32_t)N_SEND * 64u];
            float2 p0 = __half22float2(*(__half2*)&y0.x), p1 = __half22float2(*(__half2*)&y0.y);
            a0.x += p0.x; a0.y += p0.y; a0.z += p1.x; a0.w += p1.y;
            float2 q0 = __half22float2(*(__half2*)&y1.x), q1 = __half22float2(*(__half2*)&y1.y);
            a1.x += q0.x; a1.y += q0.y; a1.z += q1.x; a1.w += q1.y;
        }
        if (i < nB) {   // stream B
            const int e = mid + i;
            const int s = idx_send[e];
            const float4 ea = ea4[e];
            float t0 = b0.x + ea.x * w0.x + ea.y * w1.x + ea.z * w2.x + ea.w * w3.x;
            float t1 = b0.y + ea.x * w0.y + ea.y * w1.y + ea.z * w2.y + ea.w * w3.y;
            float t2 = b0.z + ea.x * w0.z + ea.y * w1.z + ea.z * w2.z + ea.w * w3.z;
            float t3 = b0.w + ea.x * w0.w + ea.y * w1.w + ea.z * w2.w + ea.w * w3.w;
            float2 g01 = __half22float2(gelu_h2(__floats2half2_rn(t0, t1)));
            float2 g23 = __half22float2(gelu_h2(__floats2half2_rn(t2, t3)));
            aG.x += g01.x; aG.y += g01.y; aG.z += g23.x; aG.w += g23.y;
            uint32_t off = (uint32_t)s * 64u + (uint32_t)q;
            uint2 y0 = Y4[off];
            uint2 y1 = Y4[off + (uint32_t)N_SEND * 64u];
            float2 p0 = __half22float2(*(__half2*)&y0.x), p1 = __half22float2(*(__half2*)&y0.y);
            a0.x += p0.x; a0.y += p0.y; a0.z += p1.x; a0.w += p1.y;
            float2 q0 = __half22float2(*(__half2*)&y1.x), q1 = __half22float2(*(__half2*)&y1.y);
            a1.x += q0.x; a1.y += q0.y; a1.z += q1.x; a1.w += q1.y;
        }
    }
    uint2 u;
    __half2 h01, h23;
    h01 = __floats2half2_rn(a0.x, a0.y); h23 = __floats2half2_rn(a0.z, a0.w);
    u.x = *(uint32_t*)&h01; u.y = *(uint32_t*)&h23;
    ((uint2*)d_Yacc)[(uint32_t)r * 64u + q] = u;
    h01 = __floats2half2_rn(a1.x, a1.y); h23 = __floats2half2_rn(a1.z, a1.w);
    u.x = *(uint32_t*)&h01; u.y = *(uint32_t*)&h23;
    ((uint2*)d_Yacc)[((uint32_t)N_REC + (uint32_t)r) * 64u + q] = u;
    h01 = __floats2half2_rn(aG.x, aG.y); h23 = __floats2half2_rn(aG.z, aG.w);
    u.x = *(uint32_t*)&h01; u.y = *(uint32_t*)&h23;
    ((uint2*)d_AccG)[(uint32_t)r * 64u + q] = u;
}

// ---------------- gemm_y: Y = x @ W1a with in-kernel fp32->hi/lo split ----------------
#define YA_BUF  0u
#define YB_BUF  131072u
#define YBUF_SZ 16384u
#define SMEM_Y_TOTAL (131072 + 3 * 16384)

__global__ __launch_bounds__(256, 1) void gemm_y(const float* __restrict__ x) {
    extern __shared__ char smem[];
    const uint32_t sb = (uint32_t)__cvta_generic_to_shared(smem);
    const int tid = threadIdx.x;
    const int tileN = blockIdx.x, tileM = blockIdx.y;
    const int wid = tid >> 5, lane = tid & 31;
    const int wm = (wid >> 2) * 64, wn = (wid & 3) * 32;

    const __half* Bg = d_B1Y;
    const size_t Bbase = (size_t)tileN * 128 * 512;

    #define LOADB(c, buf) do {                                               \
        uint32_t s_ = sb + YB_BUF + (uint32_t)(buf) * YBUF_SZ;               \
        _Pragma("unroll")                                                    \
        for (int i = 0; i < 4; i++) {                                        \
            int lin = i * 256 + tid;                                         \
            int rr_ = lin >> 3, cu_ = lin & 7;                               \
            uint32_t sa = s_ + (uint32_t)rr_ * 128u + (uint32_t)((cu_ ^ (rr_ & 7)) << 4); \
            CP_ASYNC16(sa, Bg + Bbase + (size_t)rr_ * 512 + (c) * 64 + cu_ * 8); \
        }                                                                    \
        CP_COMMIT();                                                         \
    } while (0)

    LOADB(0, 0); LOADB(1, 1); LOADB(2, 2);

    const float* xg = x + (size_t)tileM * 128 * DD;
    #pragma unroll
    for (int c = 0; c < 8; c++) {
        const int colbase = (c & 3) * 64;
        const bool lo = (c >= 4);
        char* abase = smem + YA_BUF + c * 16384;
        #pragma unroll
        for (int i = 0; i < 4; i++) {
            int lin = i * 256 + tid;
            int rr_ = lin >> 3, cu_ = lin & 7;
            const float4* gp = (const float4*)(xg + (size_t)rr_ * DD + colbase + cu_ * 8);
            float4 f0 = gp[0], f1 = gp[1];
            __half h[8];
            if (!lo) {
                h[0] = __float2half_rn(f0.x); h[1] = __float2half_rn(f0.y);
                h[2] = __float2half_rn(f0.z); h[3] = __float2half_rn(f0.w);
                h[4] = __float2half_rn(f1.x); h[5] = __float2half_rn(f1.y);
                h[6] = __float2half_rn(f1.z); h[7] = __float2half_rn(f1.w);
            } else {
                h[0] = __float2half_rn(f0.x - __half2float(__float2half_rn(f0.x)));
                h[1] = __float2half_rn(f0.y - __half2float(__float2half_rn(f0.y)));
                h[2] = __float2half_rn(f0.z - __half2float(__float2half_rn(f0.z)));
                h[3] = __float2half_rn(f0.w - __half2float(__float2half_rn(f0.w)));
                h[4] = __float2half_rn(f1.x - __half2float(__float2half_rn(f1.x)));
                h[5] = __float2half_rn(f1.y - __half2float(__float2half_rn(f1.y)));
                h[6] = __float2half_rn(f1.z - __half2float(__float2half_rn(f1.z)));
                h[7] = __float2half_rn(f1.w - __half2float(__float2half_rn(f1.w)));
            }
            *(uint4*)(abase + rr_ * 128 + ((cu_ ^ (rr_ & 7)) << 4)) = *(uint4*)h;
        }
    }
    __syncthreads();

    const int sub = lane >> 3, rr8 = lane & 7;
    const int Ar0 = wm + ((sub & 1) << 3) + rr8;
    const int aSel = sub >> 1;
    const int Ar7 = Ar0 & 7;
    const int Bn0 = wn + ((sub >> 1) << 3) + rr8;
    const int bSel = sub & 1;
    const int Bn7 = Bn0 & 7;

    float acc[64];
    #pragma unroll
    for (int i = 0; i < 64; i++) acc[i] = 0.f;

    #pragma unroll
    for (int c = 0; c < 8; c++) {
        if (7 - c >= 2)      { CP_WAIT(2); }
        else if (7 - c == 1) { CP_WAIT(1); }
        else                 { CP_WAIT(0); }
        __syncthreads();
        const uint32_t sA = sb + YA_BUF + (uint32_t)c * 16384u;
        const uint32_t sB = sb + YB_BUF + (uint32_t)(c % 3) * YBUF_SZ;
        #pragma unroll
        for (int kk = 0; kk < 4; kk++) {
            uint32_t bh[8];
            #pragma unroll
            for (int p = 0; p < 2; p++) {
                int cB = kk * 2 + bSel;
                uint32_t boff = (uint32_t)(Bn0 + p * 16) * 128u + (uint32_t)((cB ^ Bn7) << 4);
                ldsm4(&bh[p * 4], sB + boff);
            }
            #pragma unroll
            for (int t = 0; t < 4; t++) {
                int cA = kk * 2 + aSel;
                uint32_t aoff = (uint32_t)(Ar0 + t * 16) * 128u + (uint32_t)((cA ^ Ar7) << 4);
                uint32_t ah[4];
                ldsm4(ah, sA + aoff);
                #pragma unroll
                for (int n = 0; n < 4; n++)
                    mma16816(&acc[(t * 4 + n) * 4], ah, &bh[(n >> 1) * 4 + (n & 1) * 2]);
            }
        }
        __syncthreads();
        if (c + 3 < 8) LOADB(c + 3, c % 3);
    }
    #undef LOADB

    const int gid = lane >> 2, qid = lane & 3;
    #pragma unroll
    for (int t = 0; t < 4; t++) {
        #pragma unroll
        for (int n = 0; n < 4; n++) {
            float* a4 = &acc[(t * 4 + n) * 4];
            size_t Rg = (size_t)tileM * 128 + wm + t * 16 + gid;
            int C = tileN * 128 + wn + n * 8 + qid * 2;
            *(__half2*)&d_Y[Rg * DD + C] = __floats2half2_rn(a4[0], a4[1]);
            *(__half2*)&d_Y[(Rg + 8) * DD + C] = __floats2half2_rn(a4[2], a4[3]);
        }
    }
}

// ---------------- HMMA GEMM (KD=256): MODE 3 = H->gelu->Amid; MODE 0 = final ----------------
#define SM_BIAS 0u
#define SM_BC   1024u
#define SM_CNT  2048u
#define SM_BUF  4096u
#define BUF_SZ  32768u
#define SMEM_TOTAL (4096 + 3 * 32768)

__device__ __forceinline__ void load_tile256(uint32_t sdst, const __half* __restrict__ g, int tid) {
    #pragma unroll
    for (int i = 0; i < 4; i++) {
        int lin = i * 256 + tid;
        int r = lin >> 3, c = lin & 7;
        uint32_t sa = sdst + (uint32_t)r * 128u + (uint32_t)((c ^ (r & 7)) << 4);
        CP_ASYNC16(sa, g + (size_t)r * 256 + c * 8);
    }
}

template <int MODE>
__global__ __launch_bounds__(256, 1) void gemm_hmma(const float* __restrict__ bias,
                                                    float* __restrict__ outp) {
    extern __shared__ char smem[];
    const uint32_t sb = (uint32_t)__cvta_generic_to_shared(smem);
    const int tid = threadIdx.x;
    const int tileN = blockIdx.x, tileM = blockIdx.y;
    const int wid = tid >> 5, lane = tid & 31;
    const int wm = (wid >> 2) * 64, wn = (wid & 3) * 32;

    const __half* Ag = (MODE == 3) ? d_AccG : d_Amid;
    const __half* Bg = (MODE == 3) ? d_Bg   : d_B2;

    if (tid < 128) {
        ((float*)(smem + SM_BIAS))[tid] = bias[tileN * 128 + tid];
        if (MODE == 3) {
            ((float*)(smem + SM_BC))[tid] = d_bc[tileN * 128 + tid];
            int R = tileM * 128 + tid;
            ((float*)(smem + SM_CNT))[tid] = (float)(d_offs[R + 1] - d_offs[R]);
        }
    }

    const size_t Abase = (size_t)tileM * 128 * 256;
    const size_t Bbase = (size_t)tileN * 128 * 256;

    #define LOAD_CHUNK(c, buf) do {                                         \
        uint32_t s_ = sb + SM_BUF + (uint32_t)(buf) * BUF_SZ;               \
        load_tile256(s_,          Ag + Abase + (c) * 64, tid);              \
        load_tile256(s_ + 16384u, Bg + Bbase + (c) * 64, tid);              \
        CP_COMMIT();                                                        \
    } while (0)

    LOAD_CHUNK(0, 0); LOAD_CHUNK(1, 1); LOAD_CHUNK(2, 2);

    const int sub = lane >> 3, rr8 = lane & 7;
    const int Ar0 = wm + ((sub & 1) << 3) + rr8;
    const int aSel = sub >> 1;
    const int Ar7 = Ar0 & 7;
    const int Bn0 = wn + ((sub >> 1) << 3) + rr8;
    const int bSel = sub & 1;
    const int Bn7 = Bn0 & 7;

    float acc[64];
    #pragma unroll
    for (int i = 0; i < 64; i++) acc[i] = 0.f;

    #pragma unroll
    for (int c = 0; c < 4; c++) {
        if (3 - c >= 2)      { CP_WAIT(2); }
        else if (3 - c == 1) { CP_WAIT(1); }
        else                 { CP_WAIT(0); }
        __syncthreads();

        const uint32_t sB0 = sb + SM_BUF + (uint32_t)(c % 3) * BUF_SZ;
        const uint32_t sA = sB0, sB = sB0 + 16384u;

        #pragma unroll
        for (int kk = 0; kk < 4; kk++) {
            uint32_t bh[8];
            #pragma unroll
            for (int p = 0; p < 2; p++) {
                int cB = kk * 2 + bSel;
                uint32_t boff = (uint32_t)(Bn0 + p * 16) * 128u + (uint32_t)((cB ^ Bn7) << 4);
                ldsm4(&bh[p * 4], sB + boff);
            }
            #pragma unroll
            for (int t = 0; t < 4; t++) {
                int cA = kk * 2 + aSel;
                uint32_t aoff = (uint32_t)(Ar0 + t * 16) * 128u + (uint32_t)((cA ^ Ar7) << 4);
                uint32_t ah[4];
                ldsm4(ah, sA + aoff);
                #pragma unroll
                for (int n = 0; n < 4; n++)
                    mma16816(&acc[(t * 4 + n) * 4], ah, &bh[(n >> 1) * 4 + (n & 1) * 2]);
            }
        }
        __syncthreads();
        if (c + 3 < 4) LOAD_CHUNK(c + 3, c % 3);
    }
    #undef LOAD_CHUNK

    const int gid = lane >> 2, qid = lane & 3;
    const float* sbias = (const float*)(smem + SM_BIAS);
    const float* sbc   = (const float*)(smem + SM_BC);
    const float* scnt  = (const float*)(smem + SM_CNT);

    #pragma unroll
    for (int t = 0; t < 4; t++) {
        #pragma unroll
        for (int n = 0; n < 4; n++) {
            float* a4 = &acc[(t * 4 + n) * 4];
            int rl = wm + t * 16 + gid;
            int cl = wn + n * 8 + qid * 2;
            size_t Rg = (size_t)tileM * 128 + rl;
            int C  = tileN * 128 + cl;
            if (MODE == 3) {
                float b0 = sbias[cl], b1 = sbias[cl + 1];
                float bc0 = sbc[cl], bc1 = sbc[cl + 1];
                float cf0 = scnt[rl], cf1 = scnt[rl + 8];
                float s00 = a4[0] + b0 + cf0 * bc0, s01 = a4[1] + b1 + cf0 * bc1;
                float s10 = a4[2] + b0 + cf1 * bc0, s11 = a4[3] + b1 + cf1 * bc1;
                __half2 y00 = *(const __half2*)&d_Yacc[Rg * DD + C];
                __half2 y01 = *(const __half2*)&d_Yacc[(Rg + 8) * DD + C];
                __half2 y10 = *(const __half2*)&d_Yacc[((size_t)N_REC + Rg) * DD + C];
                __half2 y11 = *(const __half2*)&d_Yacc[((size_t)N_REC + Rg + 8) * DD + C];
                *(__half2*)&d_Amid[Rg * DD + C] = __floats2half2_rn(
                    gelu_mufu(s00 + __low2float(y00)), gelu_mufu(s01 + __high2float(y00)));
                *(__half2*)&d_Amid[(Rg + 8) * DD + C] = __floats2half2_rn(
                    gelu_mufu(s10 + __low2float(y01)), gelu_mufu(s11 + __high2float(y01)));
                *(__half2*)&d_Amid[((size_t)N_REC + Rg) * DD + C] = __floats2half2_rn(
                    gelu_mufu(s00 + __low2float(y10)), gelu_mufu(s01 + __high2float(y10)));
                *(__half2*)&d_Amid[((size_t)N_REC + Rg + 8) * DD + C] = __floats2half2_rn(
                    gelu_mufu(s10 + __low2float(y11)), gelu_mufu(s11 + __high2float(y11)));
            } else {
                float b0 = sbias[cl], b1 = sbias[cl + 1];
                *(float2*)&outp[Rg * DD + C] = make_float2(a4[0] + b0, a4[1] + b1);
                *(float2*)&outp[(Rg + 8) * DD + C] = make_float2(a4[2] + b0, a4[3] + b1);
            }
        }
    }
}

// ---------------- launch ----------------
extern "C" void kernel_launch(void* const* d_in, const int* in_sizes, int n_in,
                              void* d_out, int out_size) {
    const float* x         = (const float*)d_in[0];
    const float* edge_attr = (const float*)d_in[1];
    const int*   idx_send  = (const int*)d_in[2];
    const int*   idx_rec   = (const int*)d_in[3];
    const float* We1       = (const float*)d_in[4];
    const float* be1       = (const float*)d_in[5];
    const float* We2       = (const float*)d_in[6];
    const float* be2       = (const float*)d_in[7];
    const float* Wl1       = (const float*)d_in[8];
    const float* bl1       = (const float*)d_in[9];
    const float* Wl2       = (const float*)d_in[10];
    const float* bl2       = (const float*)d_in[11];
    float* out = (float*)d_out;

    static bool attr_done = false;
    if (!attr_done) {
        cudaFuncSetAttribute(gemm_y, cudaFuncAttributeMaxDynamicSharedMemorySize, SMEM_Y_TOTAL);
        cudaFuncSetAttribute(gemm_hmma<3>, cudaFuncAttributeMaxDynamicSharedMemorySize, SMEM_TOTAL);
        cudaFuncSetAttribute(gemm_hmma<0>, cudaFuncAttributeMaxDynamicSharedMemorySize, SMEM_TOTAL);
        attr_done = true;
    }

    prep_all<<<1025, 256>>>(Wl1, We2, be2, Wl2);
    seg_offs_kernel<<<(NE + 255) / 256, 256>>>(idx_rec);
    gemm_y<<<dim3(2, NROWX / 128), 256, SMEM_Y_TOTAL>>>(x);                     // Y = x @ W1a
    edge_kernel<<<N_REC / 4, 256>>>(edge_attr, idx_send, We1, be1);
    gemm_hmma<3><<<dim3(2, N_REC / 128), 256, SMEM_TOTAL>>>(bl1, nullptr);      // H -> gelu -> Amid
    gemm_hmma<0><<<dim3(2, MTOT / 128), 256, SMEM_TOTAL>>>(bl2, out);           // out
}

// round 13
// speedup vs baseline: 1.4191x; 1.1614x over previous
#include <cuda_runtime.h>
#include <cuda_fp16.h>
#include <cstdint>

#define N_SEND 12288
#define N_REC  49152
#define NE     196608
#define DD     256
#define MTOT   98304
#define NROWX  24576   // 2 * N_SEND

// ---------------- static device scratch ----------------
__device__ __half d_Y[(size_t)NROWX * DD];     // Y = x @ W1a   (fp16)
__device__ __half d_Yacc[(size_t)MTOT * DD];   // segsum(Y[idx_send]) per batch
__device__ __half d_AccG[(size_t)N_REC * DD];  // segsum(gelu(edge mlp))
__device__ __half d_Amid[(size_t)MTOT * DD];   // gelu(H) fp16
__device__ __half d_B1Y[DD * 512];             // W1a^T duplicated (hi|lo split-K)
__device__ __half d_Bg[DD * DD];               // (We2 @ Wl1[256:])^T
__device__ __half d_B2[DD * DD];               // Wl2^T
__device__ float  d_bc[DD];
__device__ int    d_offs[N_REC + 1];

// ---------------- gelu ----------------
__device__ __forceinline__ float gelu_mufu(float v) {
    float u = 0.7978845608028654f * fmaf(0.044715f * v, v * v, v);
    float t;
    asm("ex2.approx.f32 %0, %1;" : "=f"(t) : "f"(-2.8853900817779268f * u));
    float r;
    asm("rcp.approx.f32 %0, %1;" : "=f"(r) : "f"(1.0f + t));
    return v * r;
}
// packed fp16 gelu: deg-5 tanh poly (edge args |u| < ~0.55)
__device__ __forceinline__ __half2 gelu_h2(__half2 t) {
    const __half2 c_a = __float2half2_rn(0.044715f);
    const __half2 c_s = __float2half2_rn(0.7978845608f);
    const __half2 c3  = __float2half2_rn(-0.33333333f);
    const __half2 c5  = __float2half2_rn(0.13333333f);
    const __half2 h05 = __float2half2_rn(0.5f);
    __half2 t2 = __hmul2(t, t);
    __half2 inner = __hfma2(__hmul2(c_a, t), t2, t);
    __half2 u = __hmul2(c_s, inner);
    __half2 u2 = __hmul2(u, u);
    __half2 p = __hfma2(u2, c5, c3);
    __half2 th = __hfma2(__hmul2(u, u2), p, u);
    __half2 hh = __hfma2(th, h05, h05);
    return __hmul2(t, hh);
}
__device__ __forceinline__ void ldsm4(uint32_t* r, uint32_t addr) {
    asm volatile("ldmatrix.sync.aligned.m8n8.x4.shared.b16 {%0,%1,%2,%3}, [%4];"
                 : "=r"(r[0]), "=r"(r[1]), "=r"(r[2]), "=r"(r[3]) : "r"(addr));
}
__device__ __forceinline__ void mma16816(float* c, const uint32_t* a, const uint32_t* b) {
    asm volatile("mma.sync.aligned.m16n8k16.row.col.f32.f16.f16.f32 "
                 "{%0,%1,%2,%3}, {%4,%5,%6,%7}, {%8,%9}, {%0,%1,%2,%3};"
                 : "+f"(c[0]), "+f"(c[1]), "+f"(c[2]), "+f"(c[3])
                 : "r"(a[0]), "r"(a[1]), "r"(a[2]), "r"(a[3]), "r"(b[0]), "r"(b[1]));
}
#define CP_ASYNC16(s, g) asm volatile("cp.async.cg.shared.global [%0], [%1], 16;" :: "r"(s), "l"(g))
#define CP_COMMIT()      asm volatile("cp.async.commit_group;" ::: "memory")
#define CP_WAIT(n)       asm volatile("cp.async.wait_group %0;" :: "n"(n) : "memory")

// ---------------- merged prep (B1Y, Bg, bc, B2) + seg_offs in one launch ----------------
__global__ void prep_all(const float* __restrict__ Wl1,
                         const float* __restrict__ We2,
                         const float* __restrict__ be2,
                         const float* __restrict__ Wl2,
                         const int* __restrict__ idx_rec) {
    int n = threadIdx.x;
    int b = blockIdx.x;
    if (b < 512) {
        d_B1Y[(size_t)n * 512 + b] = __float2half_rn(Wl1[(b & 255) * DD + n]);
    } else if (b < 768) {
        int j = b - 512;
        float acc = 0.f;
        #pragma unroll 4
        for (int kk = 0; kk < 256; kk++)
            acc += We2[j * 256 + kk] * Wl1[(256 + kk) * DD + n];
        d_Bg[(size_t)n * DD + j] = __float2half_rn(acc);
    } else if (b == 768) {
        float acc = 0.f;
        #pragma unroll 4
        for (int kk = 0; kk < 256; kk++)
            acc += be2[kk] * Wl1[(256 + kk) * DD + n];
        d_bc[n] = acc;
    } else if (b < 1025) {
        int k = b - 769;
        d_B2[(size_t)n * DD + k] = __float2half_rn(Wl2[k * DD + n]);
    } else {
        int e = (b - 1025) * 256 + n;
        if (e < NE) {
            int cur = idx_rec[e];
            int nxt = (e + 1 < NE) ? idx_rec[e + 1] : N_REC;
            for (int r = cur + 1; r <= nxt; r++) d_offs[r] = e + 1;
            if (e == 0) {
                for (int r = 0; r <= cur; r++) d_offs[r] = 0;
            }
        }
    }
}

// ---------------- fused gather(Y) + edge-MLP + segment sum ----------------
// 256 threads = 4 segments x 64 threads; each thread owns 4 dims; MLP in packed half2.
__global__ __launch_bounds__(256) void edge_kernel(const float* __restrict__ edge_attr,
                            const int*  __restrict__ idx_send,
                            const float* __restrict__ We1,
                            const float* __restrict__ be1) {
    const int r = blockIdx.x * 4 + (threadIdx.x >> 6);
    const int q = threadIdx.x & 63;            // owns dims [4q, 4q+4)
    const int start = d_offs[r], end = d_offs[r + 1];
    const int mid = (start + end + 1) >> 1;
    const int nA = mid - start, nB = end - mid;   // nA >= nB

    // weights as half2 pairs: [k][half] over the 4 owned dims
    const __half2 w0a = __floats2half2_rn(We1[4*q],       We1[4*q+1]);
    const __half2 w0b = __floats2half2_rn(We1[4*q+2],     We1[4*q+3]);
    const __half2 w1a = __floats2half2_rn(We1[256+4*q],   We1[256+4*q+1]);
    const __half2 w1b = __floats2half2_rn(We1[256+4*q+2], We1[256+4*q+3]);
    const __half2 w2a = __floats2half2_rn(We1[512+4*q],   We1[512+4*q+1]);
    const __half2 w2b = __floats2half2_rn(We1[512+4*q+2], We1[512+4*q+3]);
    const __half2 w3a = __floats2half2_rn(We1[768+4*q],   We1[768+4*q+1]);
    const __half2 w3b = __floats2half2_rn(We1[768+4*q+2], We1[768+4*q+3]);
    const __half2 bha = __floats2half2_rn(be1[4*q],       be1[4*q+1]);
    const __half2 bhb = __floats2half2_rn(be1[4*q+2],     be1[4*q+3]);

    const uint2* __restrict__ Y4 = (const uint2*)d_Y;   // row stride = 64 uint2
    const float4* __restrict__ ea4 = (const float4*)edge_attr;

    float4 aG = make_float4(0.f, 0.f, 0.f, 0.f);
    float4 a0 = aG, a1 = aG;

    for (int i = 0; i < nA; i++) {
        {   // stream A
            const int e = start + i;
            const int s = idx_send[e];
            const float4 ea = ea4[e];
            __half2 ex = __float2half2_rn(ea.x), ey = __float2half2_rn(ea.y);
            __half2 ez = __float2half2_rn(ea.z), ew = __float2half2_rn(ea.w);
            __half2 t0 = __hfma2(ex, w0a, bha);
            t0 = __hfma2(ey, w1a, t0); t0 = __hfma2(ez, w2a, t0); t0 = __hfma2(ew, w3a, t0);
            __half2 t1 = __hfma2(ex, w0b, bhb);
            t1 = __hfma2(ey, w1b, t1); t1 = __hfma2(ez, w2b, t1); t1 = __hfma2(ew, w3b, t1);
            float2 g01 = __half22float2(gelu_h2(t0));
            float2 g23 = __half22float2(gelu_h2(t1));
            aG.x += g01.x; aG.y += g01.y; aG.z += g23.x; aG.w += g23.y;
            uint32_t off = (uint32_t)s * 64u + (uint32_t)q;
            uint2 y0 = Y4[off];
            uint2 y1 = Y4[off + (uint32_t)N_SEND * 64u];
            float2 p0 = __half22float2(*(__half2*)&y0.x), p1 = __half22float2(*(__half2*)&y0.y);
            a0.x += p0.x; a0.y += p0.y; a0.z += p1.x; a0.w += p1.y;
            float2 q0 = __half22float2(*(__half2*)&y1.x), q1 = __half22float2(*(__half2*)&y1.y);
            a1.x += q0.x; a1.y += q0.y; a1.z += q1.x; a1.w += q1.y;
        }
        if (i < nB) {   // stream B
            const int e = mid + i;
            const int s = idx_send[e];
            const float4 ea = ea4[e];
            __half2 ex = __float2half2_rn(ea.x), ey = __float2half2_rn(ea.y);
            __half2 ez = __float2half2_rn(ea.z), ew = __float2half2_rn(ea.w);
            __half2 t0 = __hfma2(ex, w0a, bha);
            t0 = __hfma2(ey, w1a, t0); t0 = __hfma2(ez, w2a, t0); t0 = __hfma2(ew, w3a, t0);
            __half2 t1 = __hfma2(ex, w0b, bhb);
            t1 = __hfma2(ey, w1b, t1); t1 = __hfma2(ez, w2b, t1); t1 = __hfma2(ew, w3b, t1);
            float2 g01 = __half22float2(gelu_h2(t0));
            float2 g23 = __half22float2(gelu_h2(t1));
            aG.x += g01.x; aG.y += g01.y; aG.z += g23.x; aG.w += g23.y;
            uint32_t off = (uint32_t)s * 64u + (uint32_t)q;
            uint2 y0 = Y4[off];
            uint2 y1 = Y4[off + (uint32_t)N_SEND * 64u];
            float2 p0 = __half22float2(*(__half2*)&y0.x), p1 = __half22float2(*(__half2*)&y0.y);
            a0.x += p0.x; a0.y += p0.y; a0.z += p1.x; a0.w += p1.y;
            float2 q0 = __half22float2(*(__half2*)&y1.x), q1 = __half22float2(*(__half2*)&y1.y);
            a1.x += q0.x; a1.y += q0.y; a1.z += q1.x; a1.w += q1.y;
        }
    }
    uint2 u;
    __half2 h01, h23;
    h01 = __floats2half2_rn(a0.x, a0.y); h23 = __floats2half2_rn(a0.z, a0.w);
    u.x = *(uint32_t*)&h01; u.y = *(uint32_t*)&h23;
    ((uint2*)d_Yacc)[(uint32_t)r * 64u + q] = u;
    h01 = __floats2half2_rn(a1.x, a1.y); h23 = __floats2half2_rn(a1.z, a1.w);
    u.x = *(uint32_t*)&h01; u.y = *(uint32_t*)&h23;
    ((uint2*)d_Yacc)[((uint32_t)N_REC + (uint32_t)r) * 64u + q] = u;
    h01 = __floats2half2_rn(aG.x, aG.y); h23 = __floats2half2_rn(aG.z, aG.w);
    u.x = *(uint32_t*)&h01; u.y = *(uint32_t*)&h23;
    ((uint2*)d_AccG)[(uint32_t)r * 64u + q] = u;
}

// ---------------- gemm_y: Y = x @ W1a with in-kernel fp32->hi/lo split ----------------
#define YA_BUF  0u
#define YB_BUF  131072u
#define YBUF_SZ 16384u
#define SMEM_Y_TOTAL (131072 + 3 * 16384)

__global__ __launch_bounds__(256, 1) void gemm_y(const float* __restrict__ x) {
    extern __shared__ char smem[];
    const uint32_t sb = (uint32_t)__cvta_generic_to_shared(smem);
    const int tid = threadIdx.x;
    const int tileN = blockIdx.x, tileM = blockIdx.y;
    const int wid = tid >> 5, lane = tid & 31;
    const int wm = (wid >> 2) * 64, wn = (wid & 3) * 32;

    const __half* Bg = d_B1Y;
    const size_t Bbase = (size_t)tileN * 128 * 512;

    #define LOADB(c, buf) do {                                               \
        uint32_t s_ = sb + YB_BUF + (uint32_t)(buf) * YBUF_SZ;               \
        _Pragma("unroll")                                                    \
        for (int i = 0; i < 4; i++) {                                        \
            int lin = i * 256 + tid;                                         \
            int rr_ = lin >> 3, cu_ = lin & 7;                               \
            uint32_t sa = s_ + (uint32_t)rr_ * 128u + (uint32_t)((cu_ ^ (rr_ & 7)) << 4); \
            CP_ASYNC16(sa, Bg + Bbase + (size_t)rr_ * 512 + (c) * 64 + cu_ * 8); \
        }                                                                    \
        CP_COMMIT();                                                         \
    } while (0)

    LOADB(0, 0); LOADB(1, 1); LOADB(2, 2);

    const float* xg = x + (size_t)tileM * 128 * DD;
    #pragma unroll
    for (int c = 0; c < 8; c++) {
        const int colbase = (c & 3) * 64;
        const bool lo = (c >= 4);
        char* abase = smem + YA_BUF + c * 16384;
        #pragma unroll
        for (int i = 0; i < 4; i++) {
            int lin = i * 256 + tid;
            int rr_ = lin >> 3, cu_ = lin & 7;
            const float4* gp = (const float4*)(xg + (size_t)rr_ * DD + colbase + cu_ * 8);
            float4 f0 = gp[0], f1 = gp[1];
            __half h[8];
            if (!lo) {
                h[0] = __float2half_rn(f0.x); h[1] = __float2half_rn(f0.y);
                h[2] = __float2half_rn(f0.z); h[3] = __float2half_rn(f0.w);
                h[4] = __float2half_rn(f1.x); h[5] = __float2half_rn(f1.y);
                h[6] = __float2half_rn(f1.z); h[7] = __float2half_rn(f1.w);
            } else {
                h[0] = __float2half_rn(f0.x - __half2float(__float2half_rn(f0.x)));
                h[1] = __float2half_rn(f0.y - __half2float(__float2half_rn(f0.y)));
                h[2] = __float2half_rn(f0.z - __half2float(__float2half_rn(f0.z)));
                h[3] = __float2half_rn(f0.w - __half2float(__float2half_rn(f0.w)));
                h[4] = __float2half_rn(f1.x - __half2float(__float2half_rn(f1.x)));
                h[5] = __float2half_rn(f1.y - __half2float(__float2half_rn(f1.y)));
                h[6] = __float2half_rn(f1.z - __half2float(__float2half_rn(f1.z)));
                h[7] = __float2half_rn(f1.w - __half2float(__float2half_rn(f1.w)));
            }
            *(uint4*)(abase + rr_ * 128 + ((cu_ ^ (rr_ & 7)) << 4)) = *(uint4*)h;
        }
    }
    __syncthreads();

    const int sub = lane >> 3, rr8 = lane & 7;
    const int Ar0 = wm + ((sub & 1) << 3) + rr8;
    const int aSel = sub >> 1;
    const int Ar7 = Ar0 & 7;
    const int Bn0 = wn + ((sub >> 1) << 3) + rr8;
    const int bSel = sub & 1;
    const int Bn7 = Bn0 & 7;

    float acc[64];
    #pragma unroll
    for (int i = 0; i < 64; i++) acc[i] = 0.f;

    #pragma unroll
    for (int c = 0; c < 8; c++) {
        if (7 - c >= 2)      { CP_WAIT(2); }
        else if (7 - c == 1) { CP_WAIT(1); }
        else                 { CP_WAIT(0); }
        __syncthreads();
        const uint32_t sA = sb + YA_BUF + (uint32_t)c * 16384u;
        const uint32_t sB = sb + YB_BUF + (uint32_t)(c % 3) * YBUF_SZ;
        #pragma unroll
        for (int kk = 0; kk < 4; kk++) {
            uint32_t bh[8];
            #pragma unroll
            for (int p = 0; p < 2; p++) {
                int cB = kk * 2 + bSel;
                uint32_t boff = (uint32_t)(Bn0 + p * 16) * 128u + (uint32_t)((cB ^ Bn7) << 4);
                ldsm4(&bh[p * 4], sB + boff);
            }
            #pragma unroll
            for (int t = 0; t < 4; t++) {
                int cA = kk * 2 + aSel;
                uint32_t aoff = (uint32_t)(Ar0 + t * 16) * 128u + (uint32_t)((cA ^ Ar7) << 4);
                uint32_t ah[4];
                ldsm4(ah, sA + aoff);
                #pragma unroll
                for (int n = 0; n < 4; n++)
                    mma16816(&acc[(t * 4 + n) * 4], ah, &bh[(n >> 1) * 4 + (n & 1) * 2]);
            }
        }
        __syncthreads();
        if (c + 3 < 8) LOADB(c + 3, c % 3);
    }
    #undef LOADB

    const int gid = lane >> 2, qid = lane & 3;
    #pragma unroll
    for (int t = 0; t < 4; t++) {
        #pragma unroll
        for (int n = 0; n < 4; n++) {
            float* a4 = &acc[(t * 4 + n) * 4];
            size_t Rg = (size_t)tileM * 128 + wm + t * 16 + gid;
            int C = tileN * 128 + wn + n * 8 + qid * 2;
            *(__half2*)&d_Y[Rg * DD + C] = __floats2half2_rn(a4[0], a4[1]);
            *(__half2*)&d_Y[(Rg + 8) * DD + C] = __floats2half2_rn(a4[2], a4[3]);
        }
    }
}

// ---------------- HMMA GEMM (KD=256), 128x64 CTA tile, 2-stage, 3 CTAs/SM ----------------
// MODE 3 = AccG@Bg -> +Yacc/bias/cnt*bc -> gelu -> Amid (both batches); MODE 0 = Amid@B2+bl2 -> out
#define SM_BIAS 0u
#define SM_BC   256u
#define SM_CNT  512u
#define SM_BUF  1024u
#define BUF_SZ  24576u
#define SMEM_TOTAL (1024 + 2 * 24576)

template <int MODE>
__global__ __launch_bounds__(256, 3) void gemm_hmma(const float* __restrict__ bias,
                                                    float* __restrict__ outp) {
    extern __shared__ char smem[];
    const uint32_t sb = (uint32_t)__cvta_generic_to_shared(smem);
    const int tid = threadIdx.x;
    const int tileN = blockIdx.x, tileM = blockIdx.y;
    const int wid = tid >> 5, lane = tid & 31;
    const int wm = (wid >> 1) * 32, wn = (wid & 1) * 32;

    const __half* Ag = (MODE == 3) ? d_AccG : d_Amid;
    const __half* Bg = (MODE == 3) ? d_Bg   : d_B2;

    if (tid < 64) {
        ((float*)(smem + SM_BIAS))[tid] = bias[tileN * 64 + tid];
        if (MODE == 3) ((float*)(smem + SM_BC))[tid] = d_bc[tileN * 64 + tid];
    }
    if (MODE == 3 && tid < 128) {
        int R = tileM * 128 + tid;
        ((float*)(smem + SM_CNT))[tid] = (float)(d_offs[R + 1] - d_offs[R]);
    }

    const size_t Abase = (size_t)tileM * 128 * 256;
    const size_t Bbase = (size_t)tileN * 64 * 256;

    // A: 128x64 (16KB) at buf+0; B: 64x64 (8KB) at buf+16384
    #define LOAD_CHUNK(c, buf) do {                                          \
        uint32_t s_ = sb + SM_BUF + (uint32_t)(buf) * BUF_SZ;                \
        _Pragma("unroll")                                                    \
        for (int i = 0; i < 4; i++) {                                        \
            int lin = i * 256 + tid;                                         \
            int rr_ = lin >> 3, cu_ = lin & 7;                               \
            uint32_t sa = s_ + (uint32_t)rr_ * 128u + (uint32_t)((cu_ ^ (rr_ & 7)) << 4); \
            CP_ASYNC16(sa, Ag + Abase + (size_t)rr_ * 256 + (c) * 64 + cu_ * 8); \
        }                                                                    \
        _Pragma("unroll")                                                    \
        for (int i = 0; i < 2; i++) {                                        \
            int lin = i * 256 + tid;                                         \
            int rr_ = lin >> 3, cu_ = lin & 7;                               \
            uint32_t sa = s_ + 16384u + (uint32_t)rr_ * 128u + (uint32_t)((cu_ ^ (rr_ & 7)) << 4); \
            CP_ASYNC16(sa, Bg + Bbase + (size_t)rr_ * 256 + (c) * 64 + cu_ * 8); \
        }                                                                    \
        CP_COMMIT();                                                         \
    } while (0)

    LOAD_CHUNK(0, 0); LOAD_CHUNK(1, 1);

    const int sub = lane >> 3, rr8 = lane & 7;
    const int Ar0 = wm + ((sub & 1) << 3) + rr8;
    const int aSel = sub >> 1;
    const int Ar7 = Ar0 & 7;
    const int Bn0 = wn + ((sub >> 1) << 3) + rr8;
    const int bSel = sub & 1;
    const int Bn7 = Bn0 & 7;

    float acc[32];
    #pragma unroll
    for (int i = 0; i < 32; i++) acc[i] = 0.f;

    #pragma unroll
    for (int c = 0; c < 4; c++) {
        if (c < 3) { CP_WAIT(1); } else { CP_WAIT(0); }
        __syncthreads();

        const uint32_t s0 = sb + SM_BUF + (uint32_t)(c & 1) * BUF_SZ;
        const uint32_t sA = s0, sB = s0 + 16384u;

        #pragma unroll
        for (int kk = 0; kk < 4; kk++) {
            uint32_t bh[8];
            #pragma unroll
            for (int p = 0; p < 2; p++) {
                int cB = kk * 2 + bSel;
                uint32_t boff = (uint32_t)(Bn0 + p * 16) * 128u + (uint32_t)((cB ^ Bn7) << 4);
                ldsm4(&bh[p * 4], sB + boff);
            }
            #pragma unroll
            for (int t = 0; t < 2; t++) {
                int cA = kk * 2 + aSel;
                uint32_t aoff = (uint32_t)(Ar0 + t * 16) * 128u + (uint32_t)((cA ^ Ar7) << 4);
                uint32_t ah[4];
                ldsm4(ah, sA + aoff);
                #pragma unroll
                for (int n = 0; n < 4; n++)
                    mma16816(&acc[(t * 4 + n) * 4], ah, &bh[(n >> 1) * 4 + (n & 1) * 2]);
            }
        }
        __syncthreads();
        if (c + 2 < 4) LOAD_CHUNK(c + 2, c & 1);
    }
    #undef LOAD_CHUNK

    const int gid = lane >> 2, qid = lane & 3;
    const float* sbias = (const float*)(smem + SM_BIAS);
    const float* sbc   = (const float*)(smem + SM_BC);
    const float* scnt  = (const float*)(smem + SM_CNT);

    #pragma unroll
    for (int t = 0; t < 2; t++) {
        #pragma unroll
        for (int n = 0; n < 4; n++) {
            float* a4 = &acc[(t * 4 + n) * 4];
            int rl = wm + t * 16 + gid;
            int cl = wn + n * 8 + qid * 2;
            size_t Rg = (size_t)tileM * 128 + rl;
            int C  = tileN * 64 + cl;
            if (MODE == 3) {
                float b0 = sbias[cl], b1 = sbias[cl + 1];
                float bc0 = sbc[cl], bc1 = sbc[cl + 1];
                float cf0 = scnt[rl], cf1 = scnt[rl + 8];
                float s00 = a4[0] + b0 + cf0 * bc0, s01 = a4[1] + b1 + cf0 * bc1;
                float s10 = a4[2] + b0 + cf1 * bc0, s11 = a4[3] + b1 + cf1 * bc1;
                __half2 y00 = *(const __half2*)&d_Yacc[Rg * DD + C];
                __half2 y01 = *(const __half2*)&d_Yacc[(Rg + 8) * DD + C];
                __half2 y10 = *(const __half2*)&d_Yacc[((size_t)N_REC + Rg) * DD + C];
                __half2 y11 = *(const __half2*)&d_Yacc[((size_t)N_REC + Rg + 8) * DD + C];
                *(__half2*)&d_Amid[Rg * DD + C] = __floats2half2_rn(
                    gelu_mufu(s00 + __low2float(y00)), gelu_mufu(s01 + __high2float(y00)));
                *(__half2*)&d_Amid[(Rg + 8) * DD + C] = __floats2half2_rn(
                    gelu_mufu(s10 + __low2float(y01)), gelu_mufu(s11 + __high2float(y01)));
                *(__half2*)&d_Amid[((size_t)N_REC + Rg) * DD + C] = __floats2half2_rn(
                    gelu_mufu(s00 + __low2float(y10)), gelu_mufu(s01 + __high2float(y10)));
                *(__half2*)&d_Amid[((size_t)N_REC + Rg + 8) * DD + C] = __floats2half2_rn(
                    gelu_mufu(s10 + __low2float(y11)), gelu_mufu(s11 + __high2float(y11)));
            } else {
                float b0 = sbias[cl], b1 = sbias[cl + 1];
                *(float2*)&outp[Rg * DD + C] = make_float2(a4[0] + b0, a4[1] + b1);
                *(float2*)&outp[(Rg + 8) * DD + C] = make_float2(a4[2] + b0, a4[3] + b1);
            }
        }
    }
}

// ---------------- launch ----------------
extern "C" void kernel_launch(void* const* d_in, const int* in_sizes, int n_in,
                              void* d_out, int out_size) {
    const float* x         = (const float*)d_in[0];
    const float* edge_attr = (const float*)d_in[1];
    const int*   idx_send  = (const int*)d_in[2];
    const int*   idx_rec   = (const int*)d_in[3];
    const float* We1       = (const float*)d_in[4];
    const float* be1       = (const float*)d_in[5];
    const float* We2       = (const float*)d_in[6];
    const float* be2       = (const float*)d_in[7];
    const float* Wl1       = (const float*)d_in[8];
    const float* bl1       = (const float*)d_in[9];
    const float* Wl2       = (const float*)d_in[10];
    const float* bl2       = (const float*)d_in[11];
    float* out = (float*)d_out;

    static bool attr_done = false;
    if (!attr_done) {
        cudaFuncSetAttribute(gemm_y, cudaFuncAttributeMaxDynamicSharedMemorySize, SMEM_Y_TOTAL);
        cudaFuncSetAttribute(gemm_hmma<3>, cudaFuncAttributeMaxDynamicSharedMemorySize, SMEM_TOTAL);
        cudaFuncSetAttribute(gemm_hmma<0>, cudaFuncAttributeMaxDynamicSharedMemorySize, SMEM_TOTAL);
        attr_done = true;
    }

    prep_all<<<1025 + (NE + 255) / 256, 256>>>(Wl1, We2, be2, Wl2, idx_rec);
    gemm_y<<<dim3(2, NROWX / 128), 256, SMEM_Y_TOTAL>>>(x);                     // Y = x @ W1a
    edge_kernel<<<N_REC / 4, 256>>>(edge_attr, idx_send, We1, be1);
    gemm_hmma<3><<<dim3(4, N_REC / 128), 256, SMEM_TOTAL>>>(bl1, nullptr);      // H -> gelu -> Amid
    gemm_hmma<0><<<dim3(4, MTOT / 128), 256, SMEM_TOTAL>>>(bl2, out);           // out
}

// round 14
// speedup vs baseline: 1.4489x; 1.0210x over previous
#include <cuda_runtime.h>
#include <cuda_fp16.h>
#include <cstdint>

#define N_SEND 12288
#define N_REC  49152
#define NE     196608
#define DD     256
#define MTOT   98304
#define NROWX  24576   // 2 * N_SEND

// ---------------- static device scratch ----------------
// d_Y layout (batch-interleaved): uint2 index (s*64+q)*2 + b holds dims [4q,4q+4) of batch b
__device__ __align__(16) __half d_Y[(size_t)NROWX * DD];
__device__ __align__(16) __half d_Yacc[(size_t)MTOT * DD];   // segsum(Y) per batch, [m][256]
__device__ __align__(16) __half d_AccG[(size_t)N_REC * DD];  // segsum(gelu(edge mlp))
__device__ __align__(16) __half d_Amid[(size_t)MTOT * DD];   // gelu(H) fp16
__device__ __half d_B1Y[DD * 512];             // W1a^T duplicated (hi|lo split-K)
__device__ __half d_Bg[DD * DD];               // (We2 @ Wl1[256:])^T
__device__ __half d_B2[DD * DD];               // Wl2^T
__device__ float  d_bc[DD];
__device__ int    d_offs[N_REC + 1];

// ---------------- gelu ----------------
__device__ __forceinline__ float gelu_mufu(float v) {
    float u = 0.7978845608028654f * fmaf(0.044715f * v, v * v, v);
    float t;
    asm("ex2.approx.f32 %0, %1;" : "=f"(t) : "f"(-2.8853900817779268f * u));
    float r;
    asm("rcp.approx.f32 %0, %1;" : "=f"(r) : "f"(1.0f + t));
    return v * r;
}
// packed fp16 gelu: deg-5 tanh poly (edge args |u| < ~0.55)
__device__ __forceinline__ __half2 gelu_h2(__half2 t) {
    const __half2 c_a = __float2half2_rn(0.044715f);
    const __half2 c_s = __float2half2_rn(0.7978845608f);
    const __half2 c3  = __float2half2_rn(-0.33333333f);
    const __half2 c5  = __float2half2_rn(0.13333333f);
    const __half2 h05 = __float2half2_rn(0.5f);
    __half2 t2 = __hmul2(t, t);
    __half2 inner = __hfma2(__hmul2(c_a, t), t2, t);
    __half2 u = __hmul2(c_s, inner);
    __half2 u2 = __hmul2(u, u);
    __half2 p = __hfma2(u2, c5, c3);
    __half2 th = __hfma2(__hmul2(u, u2), p, u);
    __half2 hh = __hfma2(th, h05, h05);
    return __hmul2(t, hh);
}
__device__ __forceinline__ void ldsm4(uint32_t* r, uint32_t addr) {
    asm volatile("ldmatrix.sync.aligned.m8n8.x4.shared.b16 {%0,%1,%2,%3}, [%4];"
                 : "=r"(r[0]), "=r"(r[1]), "=r"(r[2]), "=r"(r[3]) : "r"(addr));
}
__device__ __forceinline__ void mma16816(float* c, const uint32_t* a, const uint32_t* b) {
    asm volatile("mma.sync.aligned.m16n8k16.row.col.f32.f16.f16.f32 "
                 "{%0,%1,%2,%3}, {%4,%5,%6,%7}, {%8,%9}, {%0,%1,%2,%3};"
                 : "+f"(c[0]), "+f"(c[1]), "+f"(c[2]), "+f"(c[3])
                 : "r"(a[0]), "r"(a[1]), "r"(a[2]), "r"(a[3]), "r"(b[0]), "r"(b[1]));
}
#define CP_ASYNC16(s, g) asm volatile("cp.async.cg.shared.global [%0], [%1], 16;" :: "r"(s), "l"(g))
#define CP_COMMIT()      asm volatile("cp.async.commit_group;" ::: "memory")
#define CP_WAIT(n)       asm volatile("cp.async.wait_group %0;" :: "n"(n) : "memory")

// ---------------- merged prep (B1Y, Bg, bc, B2) + seg_offs ----------------
__global__ void prep_all(const float* __restrict__ Wl1,
                         const float* __restrict__ We2,
                         const float* __restrict__ be2,
                         const float* __restrict__ Wl2,
                         const int* __restrict__ idx_rec) {
    int n = threadIdx.x;
    int b = blockIdx.x;
    if (b < 512) {
        d_B1Y[(size_t)n * 512 + b] = __float2half_rn(Wl1[(b & 255) * DD + n]);
    } else if (b < 768) {
        int j = b - 512;
        float acc = 0.f;
        #pragma unroll 4
        for (int kk = 0; kk < 256; kk++)
            acc += We2[j * 256 + kk] * Wl1[(256 + kk) * DD + n];
        d_Bg[(size_t)n * DD + j] = __float2half_rn(acc);
    } else if (b == 768) {
        float acc = 0.f;
        #pragma unroll 4
        for (int kk = 0; kk < 256; kk++)
            acc += be2[kk] * Wl1[(256 + kk) * DD + n];
        d_bc[n] = acc;
    } else if (b < 1025) {
        int k = b - 769;
        d_B2[(size_t)n * DD + k] = __float2half_rn(Wl2[k * DD + n]);
    } else {
        int e = (b - 1025) * 256 + n;
        if (e < NE) {
            int cur = idx_rec[e];
            int nxt = (e + 1 < NE) ? idx_rec[e + 1] : N_REC;
            for (int r = cur + 1; r <= nxt; r++) d_offs[r] = e + 1;
            if (e == 0) {
                for (int r = 0; r <= cur; r++) d_offs[r] = 0;
            }
        }
    }
}

// ---------------- fused gather(Y) + edge-MLP + segment sum (all-half2) ----------------
// 256 threads = 4 segments x 64 threads; each thread owns 4 dims of both batches.
__global__ __launch_bounds__(256) void edge_kernel(const float* __restrict__ edge_attr,
                            const int*  __restrict__ idx_send,
                            const float* __restrict__ We1,
                            const float* __restrict__ be1) {
    const int r = blockIdx.x * 4 + (threadIdx.x >> 6);
    const int q = threadIdx.x & 63;            // owns dims [4q, 4q+4)
    const int start = d_offs[r], end = d_offs[r + 1];
    const int mid = (start + end + 1) >> 1;
    const int nA = mid - start, nB = end - mid;   // nA >= nB

    const __half2 w0a = __floats2half2_rn(We1[4*q],       We1[4*q+1]);
    const __half2 w0b = __floats2half2_rn(We1[4*q+2],     We1[4*q+3]);
    const __half2 w1a = __floats2half2_rn(We1[256+4*q],   We1[256+4*q+1]);
    const __half2 w1b = __floats2half2_rn(We1[256+4*q+2], We1[256+4*q+3]);
    const __half2 w2a = __floats2half2_rn(We1[512+4*q],   We1[512+4*q+1]);
    const __half2 w2b = __floats2half2_rn(We1[512+4*q+2], We1[512+4*q+3]);
    const __half2 w3a = __floats2half2_rn(We1[768+4*q],   We1[768+4*q+1]);
    const __half2 w3b = __floats2half2_rn(We1[768+4*q+2], We1[768+4*q+3]);
    const __half2 bha = __floats2half2_rn(be1[4*q],       be1[4*q+1]);
    const __half2 bhb = __floats2half2_rn(be1[4*q+2],     be1[4*q+3]);

    const uint4* __restrict__ Yv = (const uint4*)d_Y;   // one uint4 = 4 dims x 2 batches
    const float4* __restrict__ ea4 = (const float4*)edge_attr;

    const __half2 hz = __float2half2_rn(0.f);
    __half2 g0 = hz, g1 = hz;               // AccG pairs
    __half2 p00 = hz, p01 = hz;             // batch0 Yacc pairs
    __half2 p10 = hz, p11 = hz;             // batch1 Yacc pairs

    for (int i = 0; i < nA; i++) {
        {   // stream A
            const int e = start + i;
            const int s = idx_send[e];
            const float4 ea = ea4[e];
            __half2 ex = __float2half2_rn(ea.x), ey = __float2half2_rn(ea.y);
            __half2 ez = __float2half2_rn(ea.z), ew = __float2half2_rn(ea.w);
            __half2 t0 = __hfma2(ex, w0a, bha);
            t0 = __hfma2(ey, w1a, t0); t0 = __hfma2(ez, w2a, t0); t0 = __hfma2(ew, w3a, t0);
            __half2 t1 = __hfma2(ex, w0b, bhb);
            t1 = __hfma2(ey, w1b, t1); t1 = __hfma2(ez, w2b, t1); t1 = __hfma2(ew, w3b, t1);
            g0 = __hadd2(g0, gelu_h2(t0));
            g1 = __hadd2(g1, gelu_h2(t1));
            uint4 v = Yv[(uint32_t)s * 64u + (uint32_t)q];
            p00 = __hadd2(p00, *(__half2*)&v.x); p01 = __hadd2(p01, *(__half2*)&v.y);
            p10 = __hadd2(p10, *(__half2*)&v.z); p11 = __hadd2(p11, *(__half2*)&v.w);
        }
        if (i < nB) {   // stream B
            const int e = mid + i;
            const int s = idx_send[e];
            const float4 ea = ea4[e];
            __half2 ex = __float2half2_rn(ea.x), ey = __float2half2_rn(ea.y);
            __half2 ez = __float2half2_rn(ea.z), ew = __float2half2_rn(ea.w);
            __half2 t0 = __hfma2(ex, w0a, bha);
            t0 = __hfma2(ey, w1a, t0); t0 = __hfma2(ez, w2a, t0); t0 = __hfma2(ew, w3a, t0);
            __half2 t1 = __hfma2(ex, w0b, bhb);
            t1 = __hfma2(ey, w1b, t1); t1 = __hfma2(ez, w2b, t1); t1 = __hfma2(ew, w3b, t1);
            g0 = __hadd2(g0, gelu_h2(t0));
            g1 = __hadd2(g1, gelu_h2(t1));
            uint4 v = Yv[(uint32_t)s * 64u + (uint32_t)q];
            p00 = __hadd2(p00, *(__half2*)&v.x); p01 = __hadd2(p01, *(__half2*)&v.y);
            p10 = __hadd2(p10, *(__half2*)&v.z); p11 = __hadd2(p11, *(__half2*)&v.w);
        }
    }
    uint2 u;
    u.x = *(uint32_t*)&p00; u.y = *(uint32_t*)&p01;
    ((uint2*)d_Yacc)[(uint32_t)r * 64u + q] = u;
    u.x = *(uint32_t*)&p10; u.y = *(uint32_t*)&p11;
    ((uint2*)d_Yacc)[((uint32_t)N_REC + (uint32_t)r) * 64u + q] = u;
    u.x = *(uint32_t*)&g0;  u.y = *(uint32_t*)&g1;
    ((uint2*)d_AccG)[(uint32_t)r * 64u + q] = u;
}

// ---------------- gemm_y: Y = x @ W1a, 64-row tiles, 2 CTAs/SM, interleaved output ----------------
#define YA_BUF  0u
#define YB_BUF  65536u
#define YBUF_SZ 16384u
#define SMEM_Y_TOTAL (65536 + 3 * 16384)

__global__ __launch_bounds__(256, 2) void gemm_y(const float* __restrict__ x) {
    extern __shared__ char smem[];
    const uint32_t sb = (uint32_t)__cvta_generic_to_shared(smem);
    const int tid = threadIdx.x;
    const int tileN = blockIdx.x, tileM = blockIdx.y;     // tileM: 64-row band
    const int wid = tid >> 5, lane = tid & 31;
    const int wm = (wid >> 2) * 32, wn = (wid & 3) * 32;

    const __half* Bg = d_B1Y;
    const size_t Bbase = (size_t)tileN * 128 * 512;

    #define LOADB(c, buf) do {                                               \
        uint32_t s_ = sb + YB_BUF + (uint32_t)(buf) * YBUF_SZ;               \
        _Pragma("unroll")                                                    \
        for (int i = 0; i < 4; i++) {                                        \
            int lin = i * 256 + tid;                                         \
            int rr_ = lin >> 3, cu_ = lin & 7;                               \
            uint32_t sa = s_ + (uint32_t)rr_ * 128u + (uint32_t)((cu_ ^ (rr_ & 7)) << 4); \
            CP_ASYNC16(sa, Bg + Bbase + (size_t)rr_ * 512 + (c) * 64 + cu_ * 8); \
        }                                                                    \
        CP_COMMIT();                                                         \
    } while (0)

    LOADB(0, 0); LOADB(1, 1); LOADB(2, 2);

    // A preload: 8 chunks of 64 rows x 64 cols fp16 (hi c<4, lo c>=4), 8KB each
    const float* xg = x + (size_t)tileM * 64 * DD;
    #pragma unroll
    for (int c = 0; c < 8; c++) {
        const int colbase = (c & 3) * 64;
        const bool lo = (c >= 4);
        char* abase = smem + YA_BUF + c * 8192;
        #pragma unroll
        for (int i = 0; i < 2; i++) {
            int lin = i * 256 + tid;            // 0..511 -> 64 rows x 8 cols(16B)
            int rr_ = lin >> 3, cu_ = lin & 7;
            const float4* gp = (const float4*)(xg + (size_t)rr_ * DD + colbase + cu_ * 8);
            float4 f0 = gp[0], f1 = gp[1];
            __half h[8];
            if (!lo) {
                h[0] = __float2half_rn(f0.x); h[1] = __float2half_rn(f0.y);
                h[2] = __float2half_rn(f0.z); h[3] = __float2half_rn(f0.w);
                h[4] = __float2half_rn(f1.x); h[5] = __float2half_rn(f1.y);
                h[6] = __float2half_rn(f1.z); h[7] = __float2half_rn(f1.w);
            } else {
                h[0] = __float2half_rn(f0.x - __half2float(__float2half_rn(f0.x)));
                h[1] = __float2half_rn(f0.y - __half2float(__float2half_rn(f0.y)));
                h[2] = __float2half_rn(f0.z - __half2float(__float2half_rn(f0.z)));
                h[3] = __float2half_rn(f0.w - __half2float(__float2half_rn(f0.w)));
                h[4] = __float2half_rn(f1.x - __half2float(__float2half_rn(f1.x)));
                h[5] = __float2half_rn(f1.y - __half2float(__float2half_rn(f1.y)));
                h[6] = __float2half_rn(f1.z - __half2float(__float2half_rn(f1.z)));
                h[7] = __float2half_rn(f1.w - __half2float(__float2half_rn(f1.w)));
            }
            *(uint4*)(abase + rr_ * 128 + ((cu_ ^ (rr_ & 7)) << 4)) = *(uint4*)h;
        }
    }
    __syncthreads();

    const int sub = lane >> 3, rr8 = lane & 7;
    const int Ar0 = wm + ((sub & 1) << 3) + rr8;
    const int aSel = sub >> 1;
    const int Ar7 = Ar0 & 7;
    const int Bn0 = wn + ((sub >> 1) << 3) + rr8;
    const int bSel = sub & 1;
    const int Bn7 = Bn0 & 7;

    float acc[32];
    #pragma unroll
    for (int i = 0; i < 32; i++) acc[i] = 0.f;

    #pragma unroll
    for (int c = 0; c < 8; c++) {
        if (7 - c >= 2)      { CP_WAIT(2); }
        else if (7 - c == 1) { CP_WAIT(1); }
        else                 { CP_WAIT(0); }
        __syncthreads();
        const uint32_t sA = sb + YA_BUF + (uint32_t)c * 8192u;
        const uint32_t sB = sb + YB_BUF + (uint32_t)(c % 3) * YBUF_SZ;
        #pragma unroll
        for (int kk = 0; kk < 4; kk++) {
            uint32_t bh[8];
            #pragma unroll
            for (int p = 0; p < 2; p++) {
                int cB = kk * 2 + bSel;
                uint32_t boff = (uint32_t)(Bn0 + p * 16) * 128u + (uint32_t)((cB ^ Bn7) << 4);
                ldsm4(&bh[p * 4], sB + boff);
            }
            #pragma unroll
            for (int t = 0; t < 2; t++) {
                int cA = kk * 2 + aSel;
                uint32_t aoff = (uint32_t)(Ar0 + t * 16) * 128u + (uint32_t)((cA ^ Ar7) << 4);
                uint32_t ah[4];
                ldsm4(ah, sA + aoff);
                #pragma unroll
                for (int n = 0; n < 4; n++)
                    mma16816(&acc[(t * 4 + n) * 4], ah, &bh[(n >> 1) * 4 + (n & 1) * 2]);
            }
        }
        __syncthreads();
        if (c + 3 < 8) LOADB(c + 3, c % 3);
    }
    #undef LOADB

    // epilogue: write interleaved d_Y
    const int gid = lane >> 2, qid = lane & 3;
    #pragma unroll
    for (int t = 0; t < 2; t++) {
        #pragma unroll
        for (int n = 0; n < 4; n++) {
            float* a4 = &acc[(t * 4 + n) * 4];
            int C = tileN * 128 + wn + n * 8 + qid * 2;
            int qq = C >> 2, sub4 = (C & 3) * 2;   // byte sub-offset 0 or 4
            #pragma unroll
            for (int rr = 0; rr < 2; rr++) {
                int row = tileM * 64 + wm + t * 16 + gid + rr * 8;
                int bb = (row >= N_SEND) ? 1 : 0;
                int s = row - bb * N_SEND;
                __half2 hv = __floats2half2_rn(a4[rr * 2 + 0], a4[rr * 2 + 1]);
                *(__half2*)((char*)d_Y + (((size_t)s * 64 + qq) * 2 + bb) * 8 + sub4) = hv;
            }
        }
    }
}

// ---------------- HMMA GEMM (KD=256), 128x64 CTA tile, 2-stage, 3 CTAs/SM ----------------
#define SM_BIAS 0u
#define SM_BC   256u
#define SM_CNT  512u
#define SM_BUF  1024u
#define BUF_SZ  24576u
#define SMEM_TOTAL (1024 + 2 * 24576)

template <int MODE>
__global__ __launch_bounds__(256, 3) void gemm_hmma(const float* __restrict__ bias,
                                                    float* __restrict__ outp) {
    extern __shared__ char smem[];
    const uint32_t sb = (uint32_t)__cvta_generic_to_shared(smem);
    const int tid = threadIdx.x;
    const int tileN = blockIdx.x, tileM = blockIdx.y;
    const int wid = tid >> 5, lane = tid & 31;
    const int wm = (wid >> 1) * 32, wn = (wid & 1) * 32;

    const __half* Ag = (MODE == 3) ? d_AccG : d_Amid;
    const __half* Bg = (MODE == 3) ? d_Bg   : d_B2;

    if (tid < 64) {
        ((float*)(smem + SM_BIAS))[tid] = bias[tileN * 64 + tid];
        if (MODE == 3) ((float*)(smem + SM_BC))[tid] = d_bc[tileN * 64 + tid];
    }
    if (MODE == 3 && tid < 128) {
        int R = tileM * 128 + tid;
        ((float*)(smem + SM_CNT))[tid] = (float)(d_offs[R + 1] - d_offs[R]);
    }

    const size_t Abase = (size_t)tileM * 128 * 256;
    const size_t Bbase = (size_t)tileN * 64 * 256;

    #define LOAD_CHUNK(c, buf) do {                                          \
        uint32_t s_ = sb + SM_BUF + (uint32_t)(buf) * BUF_SZ;                \
        _Pragma("unroll")                                                    \
        for (int i = 0; i < 4; i++) {                                        \
            int lin = i * 256 + tid;                                         \
            int rr_ = lin >> 3, cu_ = lin & 7;                               \
            uint32_t sa = s_ + (uint32_t)rr_ * 128u + (uint32_t)((cu_ ^ (rr_ & 7)) << 4); \
            CP_ASYNC16(sa, Ag + Abase + (size_t)rr_ * 256 + (c) * 64 + cu_ * 8); \
        }                                                                    \
        _Pragma("unroll")                                                    \
        for (int i = 0; i < 2; i++) {                                        \
            int lin = i * 256 + tid;                                         \
            int rr_ = lin >> 3, cu_ = lin & 7;                               \
            uint32_t sa = s_ + 16384u + (uint32_t)rr_ * 128u + (uint32_t)((cu_ ^ (rr_ & 7)) << 4); \
            CP_ASYNC16(sa, Bg + Bbase + (size_t)rr_ * 256 + (c) * 64 + cu_ * 8); \
        }                                                                    \
        CP_COMMIT();                                                         \
    } while (0)

    LOAD_CHUNK(0, 0); LOAD_CHUNK(1, 1);

    const int sub = lane >> 3, rr8 = lane & 7;
    const int Ar0 = wm + ((sub & 1) << 3) + rr8;
    const int aSel = sub >> 1;
    const int Ar7 = Ar0 & 7;
    const int Bn0 = wn + ((sub >> 1) << 3) + rr8;
    const int bSel = sub & 1;
    const int Bn7 = Bn0 & 7;

    float acc[32];
    #pragma unroll
    for (int i = 0; i < 32; i++) acc[i] = 0.f;

    #pragma unroll
    for (int c = 0; c < 4; c++) {
        if (c < 3) { CP_WAIT(1); } else { CP_WAIT(0); }
        __syncthreads();

        const uint32_t s0 = sb + SM_BUF + (uint32_t)(c & 1) * BUF_SZ;
        const uint32_t sA = s0, sB = s0 + 16384u;

        #pragma unroll
        for (int kk = 0; kk < 4; kk++) {
            uint32_t bh[8];
            #pragma unroll
            for (int p = 0; p < 2; p++) {
                int cB = kk * 2 + bSel;
                uint32_t boff = (uint32_t)(Bn0 + p * 16) * 128u + (uint32_t)((cB ^ Bn7) << 4);
                ldsm4(&bh[p * 4], sB + boff);
            }
            #pragma unroll
            for (int t = 0; t < 2; t++) {
                int cA = kk * 2 + aSel;
                uint32_t aoff = (uint32_t)(Ar0 + t * 16) * 128u + (uint32_t)((cA ^ Ar7) << 4);
                uint32_t ah[4];
                ldsm4(ah, sA + aoff);
                #pragma unroll
                for (int n = 0; n < 4; n++)
                    mma16816(&acc[(t * 4 + n) * 4], ah, &bh[(n >> 1) * 4 + (n & 1) * 2]);
            }
        }
        __syncthreads();
        if (c + 2 < 4) LOAD_CHUNK(c + 2, c & 1);
    }
    #undef LOAD_CHUNK

    const int gid = lane >> 2, qid = lane & 3;
    const float* sbias = (const float*)(smem + SM_BIAS);
    const float* sbc   = (const float*)(smem + SM_BC);
    const float* scnt  = (const float*)(smem + SM_CNT);

    #pragma unroll
    for (int t = 0; t < 2; t++) {
        #pragma unroll
        for (int n = 0; n < 4; n++) {
            float* a4 = &acc[(t * 4 + n) * 4];
            int rl = wm + t * 16 + gid;
            int cl = wn + n * 8 + qid * 2;
            size_t Rg = (size_t)tileM * 128 + rl;
            int C  = tileN * 64 + cl;
            if (MODE == 3) {
                float b0 = sbias[cl], b1 = sbias[cl + 1];
                float bc0 = sbc[cl], bc1 = sbc[cl + 1];
                float cf0 = scnt[rl], cf1 = scnt[rl + 8];
                float s00 = a4[0] + b0 + cf0 * bc0, s01 = a4[1] + b1 + cf0 * bc1;
                float s10 = a4[2] + b0 + cf1 * bc0, s11 = a4[3] + b1 + cf1 * bc1;
                __half2 y00 = *(const __half2*)&d_Yacc[Rg * DD + C];
                __half2 y01 = *(const __half2*)&d_Yacc[(Rg + 8) * DD + C];
                __half2 y10 = *(const __half2*)&d_Yacc[((size_t)N_REC + Rg) * DD + C];
                __half2 y11 = *(const __half2*)&d_Yacc[((size_t)N_REC + Rg + 8) * DD + C];
                *(__half2*)&d_Amid[Rg * DD + C] = __floats2half2_rn(
                    gelu_mufu(s00 + __low2float(y00)), gelu_mufu(s01 + __high2float(y00)));
                *(__half2*)&d_Amid[(Rg + 8) * DD + C] = __floats2half2_rn(
                    gelu_mufu(s10 + __low2float(y01)), gelu_mufu(s11 + __high2float(y01)));
                *(__half2*)&d_Amid[((size_t)N_REC + Rg) * DD + C] = __floats2half2_rn(
                    gelu_mufu(s00 + __low2float(y10)), gelu_mufu(s01 + __high2float(y10)));
                *(__half2*)&d_Amid[((size_t)N_REC + Rg + 8) * DD + C] = __floats2half2_rn(
                    gelu_mufu(s10 + __low2float(y11)), gelu_mufu(s11 + __high2float(y11)));
            } else {
                float b0 = sbias[cl], b1 = sbias[cl + 1];
                *(float2*)&outp[Rg * DD + C] = make_float2(a4[0] + b0, a4[1] + b1);
                *(float2*)&outp[(Rg + 8) * DD + C] = make_float2(a4[2] + b0, a4[3] + b1);
            }
        }
    }
}

// ---------------- launch ----------------
extern "C" void kernel_launch(void* const* d_in, const int* in_sizes, int n_in,
                              void* d_out, int out_size) {
    const float* x         = (const float*)d_in[0];
    const float* edge_attr = (const float*)d_in[1];
    const int*   idx_send  = (const int*)d_in[2];
    const int*   idx_rec   = (const int*)d_in[3];
    const float* We1       = (const float*)d_in[4];
    const float* be1       = (const float*)d_in[5];
    const float* We2       = (const float*)d_in[6];
    const float* be2       = (const float*)d_in[7];
    const float* Wl1       = (const float*)d_in[8];
    const float* bl1       = (const float*)d_in[9];
    const float* Wl2       = (const float*)d_in[10];
    const float* bl2       = (const float*)d_in[11];
    float* out = (float*)d_out;

    static bool attr_done = false;
    if (!attr_done) {
        cudaFuncSetAttribute(gemm_y, cudaFuncAttributeMaxDynamicSharedMemorySize, SMEM_Y_TOTAL);
        cudaFuncSetAttribute(gemm_hmma<3>, cudaFuncAttributeMaxDynamicSharedMemorySize, SMEM_TOTAL);
        cudaFuncSetAttribute(gemm_hmma<0>, cudaFuncAttributeMaxDynamicSharedMemorySize, SMEM_TOTAL);
        attr_done = true;
    }

    prep_all<<<1025 + (NE + 255) / 256, 256>>>(Wl1, We2, be2, Wl2, idx_rec);
    gemm_y<<<dim3(2, NROWX / 64), 256, SMEM_Y_TOTAL>>>(x);                      // Y (interleaved)
    edge_kernel<<<N_REC / 4, 256>>>(edge_attr, idx_send, We1, be1);
    gemm_hmma<3><<<dim3(4, N_REC / 128), 256, SMEM_TOTAL>>>(bl1, nullptr);      // H -> gelu -> Amid
    gemm_hmma<0><<<dim3(4, MTOT / 128), 256, SMEM_TOTAL>>>(bl2, out);           // out
}

// round 15
// speedup vs baseline: 1.4497x; 1.0006x over previous
#include <cuda_runtime.h>
#include <cuda_fp16.h>
#include <cstdint>

#define N_SEND 12288
#define N_REC  49152
#define NE     196608
#define DD     256
#define MTOT   98304
#define NROWX  24576   // 2 * N_SEND

// ---------------- static device scratch ----------------
// d_Y layout (batch-interleaved): uint2 index (s*64+q)*2 + b holds dims [4q,4q+4) of batch b
__device__ __align__(16) __half d_Y[(size_t)NROWX * DD];
__device__ __align__(16) __half d_Yacc[(size_t)MTOT * DD];   // segsum(Y) per batch, [m][256]
__device__ __align__(16) __half d_AccG[(size_t)N_REC * DD];  // segsum(gelu(edge mlp))
__device__ __align__(16) __half d_Amid[(size_t)MTOT * DD];   // gelu(H) fp16
__device__ __half d_B1Y[DD * 512];             // W1a^T duplicated (hi|lo split-K)
__device__ __half d_Bg[DD * DD];               // (We2 @ Wl1[256:])^T
__device__ __half d_B2[DD * DD];               // Wl2^T
__device__ float  d_bc[DD];
__device__ int    d_offs[N_REC + 1];

// ---------------- gelu ----------------
__device__ __forceinline__ float gelu_mufu(float v) {
    float u = 0.7978845608028654f * fmaf(0.044715f * v, v * v, v);
    float t;
    asm("ex2.approx.f32 %0, %1;" : "=f"(t) : "f"(-2.8853900817779268f * u));
    float r;
    asm("rcp.approx.f32 %0, %1;" : "=f"(r) : "f"(1.0f + t));
    return v * r;
}
// packed fp16 gelu: deg-5 tanh poly (edge args |u| < ~0.55)
__device__ __forceinline__ __half2 gelu_h2(__half2 t) {
    const __half2 c_a = __float2half2_rn(0.044715f);
    const __half2 c_s = __float2half2_rn(0.7978845608f);
    const __half2 c3  = __float2half2_rn(-0.33333333f);
    const __half2 c5  = __float2half2_rn(0.13333333f);
    const __half2 h05 = __float2half2_rn(0.5f);
    __half2 t2 = __hmul2(t, t);
    __half2 inner = __hfma2(__hmul2(c_a, t), t2, t);
    __half2 u = __hmul2(c_s, inner);
    __half2 u2 = __hmul2(u, u);
    __half2 p = __hfma2(u2, c5, c3);
    __half2 th = __hfma2(__hmul2(u, u2), p, u);
    __half2 hh = __hfma2(th, h05, h05);
    return __hmul2(t, hh);
}
__device__ __forceinline__ void ldsm4(uint32_t* r, uint32_t addr) {
    asm volatile("ldmatrix.sync.aligned.m8n8.x4.shared.b16 {%0,%1,%2,%3}, [%4];"
                 : "=r"(r[0]), "=r"(r[1]), "=r"(r[2]), "=r"(r[3]) : "r"(addr));
}
__device__ __forceinline__ void mma16816(float* c, const uint32_t* a, const uint32_t* b) {
    asm volatile("mma.sync.aligned.m16n8k16.row.col.f32.f16.f16.f32 "
                 "{%0,%1,%2,%3}, {%4,%5,%6,%7}, {%8,%9}, {%0,%1,%2,%3};"
                 : "+f"(c[0]), "+f"(c[1]), "+f"(c[2]), "+f"(c[3])
                 : "r"(a[0]), "r"(a[1]), "r"(a[2]), "r"(a[3]), "r"(b[0]), "r"(b[1]));
}
#define CP_ASYNC16(s, g) asm volatile("cp.async.cg.shared.global [%0], [%1], 16;" :: "r"(s), "l"(g))
#define CP_COMMIT()      asm volatile("cp.async.commit_group;" ::: "memory")
#define CP_WAIT(n)       asm volatile("cp.async.wait_group %0;" :: "n"(n) : "memory")

// ---------------- merged prep (B1Y, Bg, bc, B2) + seg_offs ----------------
__global__ void prep_all(const float* __restrict__ Wl1,
                         const float* __restrict__ We2,
                         const float* __restrict__ be2,
                         const float* __restrict__ Wl2,
                         const int* __restrict__ idx_rec) {
    int n = threadIdx.x;
    int b = blockIdx.x;
    if (b < 512) {
        d_B1Y[(size_t)n * 512 + b] = __float2half_rn(Wl1[(b & 255) * DD + n]);
    } else if (b < 768) {
        int j = b - 512;
        float acc = 0.f;
        #pragma unroll 4
        for (int kk = 0; kk < 256; kk++)
            acc += We2[j * 256 + kk] * Wl1[(256 + kk) * DD + n];
        d_Bg[(size_t)n * DD + j] = __float2half_rn(acc);
    } else if (b == 768) {
        float acc = 0.f;
        #pragma unroll 4
        for (int kk = 0; kk < 256; kk++)
            acc += be2[kk] * Wl1[(256 + kk) * DD + n];
        d_bc[n] = acc;
    } else if (b < 1025) {
        int k = b - 769;
        d_B2[(size_t)n * DD + k] = __float2half_rn(Wl2[k * DD + n]);
    } else {
        int e = (b - 1025) * 256 + n;
        if (e < NE) {
            int cur = idx_rec[e];
            int nxt = (e + 1 < NE) ? idx_rec[e + 1] : N_REC;
            for (int r = cur + 1; r <= nxt; r++) d_offs[r] = e + 1;
            if (e == 0) {
                for (int r = 0; r <= cur; r++) d_offs[r] = 0;
            }
        }
    }
}

// ---------------- fused gather(Y) + edge-MLP + segment sum (4 streams, all-half2) ----------------
// 256 threads = 4 segments x 64 threads; each thread owns 4 dims of both batches.
__global__ __launch_bounds__(256) void edge_kernel(const float* __restrict__ edge_attr,
                            const int*  __restrict__ idx_send,
                            const float* __restrict__ We1,
                            const float* __restrict__ be1) {
    const int r = blockIdx.x * 4 + (threadIdx.x >> 6);
    const int q = threadIdx.x & 63;            // owns dims [4q, 4q+4)
    const int start = d_offs[r], end = d_offs[r + 1];
    const int n = end - start;
    const int nq = (n + 3) >> 2;
    int len[4];
    #pragma unroll
    for (int j = 0; j < 4; j++) {
        int l = n - j * nq;
        len[j] = l < 0 ? 0 : (l > nq ? nq : l);
    }

    const __half2 w0a = __floats2half2_rn(We1[4*q],       We1[4*q+1]);
    const __half2 w0b = __floats2half2_rn(We1[4*q+2],     We1[4*q+3]);
    const __half2 w1a = __floats2half2_rn(We1[256+4*q],   We1[256+4*q+1]);
    const __half2 w1b = __floats2half2_rn(We1[256+4*q+2], We1[256+4*q+3]);
    const __half2 w2a = __floats2half2_rn(We1[512+4*q],   We1[512+4*q+1]);
    const __half2 w2b = __floats2half2_rn(We1[512+4*q+2], We1[512+4*q+3]);
    const __half2 w3a = __floats2half2_rn(We1[768+4*q],   We1[768+4*q+1]);
    const __half2 w3b = __floats2half2_rn(We1[768+4*q+2], We1[768+4*q+3]);
    const __half2 bha = __floats2half2_rn(be1[4*q],       be1[4*q+1]);
    const __half2 bhb = __floats2half2_rn(be1[4*q+2],     be1[4*q+3]);

    const uint4* __restrict__ Yv = (const uint4*)d_Y;   // one uint4 = 4 dims x 2 batches
    const float4* __restrict__ ea4 = (const float4*)edge_attr;

    const __half2 hz = __float2half2_rn(0.f);
    __half2 g0 = hz, g1 = hz;
    __half2 p00 = hz, p01 = hz;
    __half2 p10 = hz, p11 = hz;

    #define PROC(eidx) do {                                                    \
        const int s_ = idx_send[eidx];                                         \
        const float4 ea_ = ea4[eidx];                                          \
        __half2 ex_ = __float2half2_rn(ea_.x), ey_ = __float2half2_rn(ea_.y);  \
        __half2 ez_ = __float2half2_rn(ea_.z), ew_ = __float2half2_rn(ea_.w);  \
        __half2 t0_ = __hfma2(ex_, w0a, bha);                                  \
        t0_ = __hfma2(ey_, w1a, t0_); t0_ = __hfma2(ez_, w2a, t0_);            \
        t0_ = __hfma2(ew_, w3a, t0_);                                          \
        __half2 t1_ = __hfma2(ex_, w0b, bhb);                                  \
        t1_ = __hfma2(ey_, w1b, t1_); t1_ = __hfma2(ez_, w2b, t1_);            \
        t1_ = __hfma2(ew_, w3b, t1_);                                          \
        g0 = __hadd2(g0, gelu_h2(t0_));                                        \
        g1 = __hadd2(g1, gelu_h2(t1_));                                        \
        uint4 v_ = Yv[(uint32_t)s_ * 64u + (uint32_t)q];                       \
        p00 = __hadd2(p00, *(__half2*)&v_.x); p01 = __hadd2(p01, *(__half2*)&v_.y); \
        p10 = __hadd2(p10, *(__half2*)&v_.z); p11 = __hadd2(p11, *(__half2*)&v_.w); \
    } while (0)

    for (int i = 0; i < nq; i++) {
        if (i < len[0]) PROC(start + i);
        if (i < len[1]) PROC(start + nq + i);
        if (i < len[2]) PROC(start + 2 * nq + i);
        if (i < len[3]) PROC(start + 3 * nq + i);
    }
    #undef PROC

    uint2 u;
    u.x = *(uint32_t*)&p00; u.y = *(uint32_t*)&p01;
    ((uint2*)d_Yacc)[(uint32_t)r * 64u + q] = u;
    u.x = *(uint32_t*)&p10; u.y = *(uint32_t*)&p11;
    ((uint2*)d_Yacc)[((uint32_t)N_REC + (uint32_t)r) * 64u + q] = u;
    u.x = *(uint32_t*)&g0;  u.y = *(uint32_t*)&g1;
    ((uint2*)d_AccG)[(uint32_t)r * 64u + q] = u;
}

// ---------------- gemm_y: Y = x @ W1a, 64-row tiles, single-barrier pipeline ----------------
#define YA_BUF  0u
#define YB_BUF  65536u
#define YBUF_SZ 16384u
#define SMEM_Y_TOTAL (65536 + 3 * 16384)

__global__ __launch_bounds__(256, 2) void gemm_y(const float* __restrict__ x) {
    extern __shared__ char smem[];
    const uint32_t sb = (uint32_t)__cvta_generic_to_shared(smem);
    const int tid = threadIdx.x;
    const int tileN = blockIdx.x, tileM = blockIdx.y;     // tileM: 64-row band
    const int wid = tid >> 5, lane = tid & 31;
    const int wm = (wid >> 2) * 32, wn = (wid & 3) * 32;

    const __half* Bg = d_B1Y;
    const size_t Bbase = (size_t)tileN * 128 * 512;

    #define LOADB(c, buf) do {                                               \
        uint32_t s_ = sb + YB_BUF + (uint32_t)(buf) * YBUF_SZ;               \
        _Pragma("unroll")                                                    \
        for (int i = 0; i < 4; i++) {                                        \
            int lin = i * 256 + tid;                                         \
            int rr_ = lin >> 3, cu_ = lin & 7;                               \
            uint32_t sa = s_ + (uint32_t)rr_ * 128u + (uint32_t)((cu_ ^ (rr_ & 7)) << 4); \
            CP_ASYNC16(sa, Bg + Bbase + (size_t)rr_ * 512 + (c) * 64 + cu_ * 8); \
        }                                                                    \
        CP_COMMIT();                                                         \
    } while (0)

    LOADB(0, 0); LOADB(1, 1);

    // A preload: 8 chunks of 64 rows x 64 cols fp16 (hi c<4, lo c>=4), 8KB each
    const float* xg = x + (size_t)tileM * 64 * DD;
    #pragma unroll
    for (int c = 0; c < 8; c++) {
        const int colbase = (c & 3) * 64;
        const bool lo = (c >= 4);
        char* abase = smem + YA_BUF + c * 8192;
        #pragma unroll
        for (int i = 0; i < 2; i++) {
            int lin = i * 256 + tid;
            int rr_ = lin >> 3, cu_ = lin & 7;
            const float4* gp = (const float4*)(xg + (size_t)rr_ * DD + colbase + cu_ * 8);
            float4 f0 = gp[0], f1 = gp[1];
            __half h[8];
            if (!lo) {
                h[0] = __float2half_rn(f0.x); h[1] = __float2half_rn(f0.y);
                h[2] = __float2half_rn(f0.z); h[3] = __float2half_rn(f0.w);
                h[4] = __float2half_rn(f1.x); h[5] = __float2half_rn(f1.y);
                h[6] = __float2half_rn(f1.z); h[7] = __float2half_rn(f1.w);
            } else {
                h[0] = __float2half_rn(f0.x - __half2float(__float2half_rn(f0.x)));
                h[1] = __float2half_rn(f0.y - __half2float(__float2half_rn(f0.y)));
                h[2] = __float2half_rn(f0.z - __half2float(__float2half_rn(f0.z)));
                h[3] = __float2half_rn(f0.w - __half2float(__float2half_rn(f0.w)));
                h[4] = __float2half_rn(f1.x - __half2float(__float2half_rn(f1.x)));
                h[5] = __float2half_rn(f1.y - __half2float(__float2half_rn(f1.y)));
                h[6] = __float2half_rn(f1.z - __half2float(__float2half_rn(f1.z)));
                h[7] = __float2half_rn(f1.w - __half2float(__float2half_rn(f1.w)));
            }
            *(uint4*)(abase + rr_ * 128 + ((cu_ ^ (rr_ & 7)) << 4)) = *(uint4*)h;
        }
    }

    const int sub = lane >> 3, rr8 = lane & 7;
    const int Ar0 = wm + ((sub & 1) << 3) + rr8;
    const int aSel = sub >> 1;
    const int Ar7 = Ar0 & 7;
    const int Bn0 = wn + ((sub >> 1) << 3) + rr8;
    const int bSel = sub & 1;
    const int Bn7 = Bn0 & 7;

    float acc[32];
    #pragma unroll
    for (int i = 0; i < 32; i++) acc[i] = 0.f;

    #pragma unroll
    for (int c = 0; c < 8; c++) {
        if (c < 7) { CP_WAIT(1); } else { CP_WAIT(0); }
        __syncthreads();
        if (c + 2 < 8) LOADB(c + 2, (c + 2) % 3);
        const uint32_t sA = sb + YA_BUF + (uint32_t)c * 8192u;
        const uint32_t sB = sb + YB_BUF + (uint32_t)(c % 3) * YBUF_SZ;
        #pragma unroll
        for (int kk = 0; kk < 4; kk++) {
            uint32_t bh[8];
            #pragma unroll
            for (int p = 0; p < 2; p++) {
                int cB = kk * 2 + bSel;
                uint32_t boff = (uint32_t)(Bn0 + p * 16) * 128u + (uint32_t)((cB ^ Bn7) << 4);
                ldsm4(&bh[p * 4], sB + boff);
            }
            #pragma unroll
            for (int t = 0; t < 2; t++) {
                int cA = kk * 2 + aSel;
                uint32_t aoff = (uint32_t)(Ar0 + t * 16) * 128u + (uint32_t)((cA ^ Ar7) << 4);
                uint32_t ah[4];
                ldsm4(ah, sA + aoff);
                #pragma unroll
                for (int n = 0; n < 4; n++)
                    mma16816(&acc[(t * 4 + n) * 4], ah, &bh[(n >> 1) * 4 + (n & 1) * 2]);
            }
        }
    }
    #undef LOADB

    // epilogue: write interleaved d_Y
    const int gid = lane >> 2, qid = lane & 3;
    #pragma unroll
    for (int t = 0; t < 2; t++) {
        #pragma unroll
        for (int n = 0; n < 4; n++) {
            float* a4 = &acc[(t * 4 + n) * 4];
            int C = tileN * 128 + wn + n * 8 + qid * 2;
            int qq = C >> 2, sub4 = (C & 3) * 2;
            #pragma unroll
            for (int rr = 0; rr < 2; rr++) {
                int row = tileM * 64 + wm + t * 16 + gid + rr * 8;
                int bb = (row >= N_SEND) ? 1 : 0;
                int s = row - bb * N_SEND;
                __half2 hv = __floats2half2_rn(a4[rr * 2 + 0], a4[rr * 2 + 1]);
                *(__half2*)((char*)d_Y + (((size_t)s * 64 + qq) * 2 + bb) * 8 + sub4) = hv;
            }
        }
    }
}

// ---------------- HMMA GEMM (KD=256), 128x64 tile, 3-buffer single-barrier, 3 CTAs/SM ----------------
#define SM_BIAS 0u
#define SM_BC   256u
#define SM_CNT  512u
#define SM_BUF  1024u
#define BUF_SZ  24576u
#define SMEM_TOTAL (1024 + 3 * 24576)

template <int MODE>
__global__ __launch_bounds__(256, 3) void gemm_hmma(const float* __restrict__ bias,
                                                    float* __restrict__ outp) {
    extern __shared__ char smem[];
    const uint32_t sb = (uint32_t)__cvta_generic_to_shared(smem);
    const int tid = threadIdx.x;
    const int tileN = blockIdx.x, tileM = blockIdx.y;
    const int wid = tid >> 5, lane = tid & 31;
    const int wm = (wid >> 1) * 32, wn = (wid & 1) * 32;

    const __half* Ag = (MODE == 3) ? d_AccG : d_Amid;
    const __half* Bg = (MODE == 3) ? d_Bg   : d_B2;

    if (tid < 64) {
        ((float*)(smem + SM_BIAS))[tid] = bias[tileN * 64 + tid];
        if (MODE == 3) ((float*)(smem + SM_BC))[tid] = d_bc[tileN * 64 + tid];
    }
    if (MODE == 3 && tid < 128) {
        int R = tileM * 128 + tid;
        ((float*)(smem + SM_CNT))[tid] = (float)(d_offs[R + 1] - d_offs[R]);
    }

    const size_t Abase = (size_t)tileM * 128 * 256;
    const size_t Bbase = (size_t)tileN * 64 * 256;

    #define LOAD_CHUNK(c, buf) do {                                          \
        uint32_t s_ = sb + SM_BUF + (uint32_t)(buf) * BUF_SZ;                \
        _Pragma("unroll")                                                    \
        for (int i = 0; i < 4; i++) {                                        \
            int lin = i * 256 + tid;                                         \
            int rr_ = lin >> 3, cu_ = lin & 7;                               \
            uint32_t sa = s_ + (uint32_t)rr_ * 128u + (uint32_t)((cu_ ^ (rr_ & 7)) << 4); \
            CP_ASYNC16(sa, Ag + Abase + (size_t)rr_ * 256 + (c) * 64 + cu_ * 8); \
        }                                                                    \
        _Pragma("unroll")                                                    \
        for (int i = 0; i < 2; i++) {                                        \
            int lin = i * 256 + tid;                                         \
            int rr_ = lin >> 3, cu_ = lin & 7;                               \
            uint32_t sa = s_ + 16384u + (uint32_t)rr_ * 128u + (uint32_t)((cu_ ^ (rr_ & 7)) << 4); \
            CP_ASYNC16(sa, Bg + Bbase + (size_t)rr_ * 256 + (c) * 64 + cu_ * 8); \
        }                                                                    \
        CP_COMMIT();                                                         \
    } while (0)

    LOAD_CHUNK(0, 0); LOAD_CHUNK(1, 1);

    const int sub = lane >> 3, rr8 = lane & 7;
    const int Ar0 = wm + ((sub & 1) << 3) + rr8;
    const int aSel = sub >> 1;
    const int Ar7 = Ar0 & 7;
    const int Bn0 = wn + ((sub >> 1) << 3) + rr8;
    const int bSel = sub & 1;
    const int Bn7 = Bn0 & 7;

    float acc[32];
    #pragma unroll
    for (int i = 0; i < 32; i++) acc[i] = 0.f;

    #pragma unroll
    for (int c = 0; c < 4; c++) {
        if (c < 3) { CP_WAIT(1); } else { CP_WAIT(0); }
        __syncthreads();
        if (c + 2 < 4) LOAD_CHUNK(c + 2, (c + 2) % 3);

        const uint32_t s0 = sb + SM_BUF + (uint32_t)(c % 3) * BUF_SZ;
        const uint32_t sA = s0, sB = s0 + 16384u;

        #pragma unroll
        for (int kk = 0; kk < 4; kk++) {
            uint32_t bh[8];
            #pragma unroll
            for (int p = 0; p < 2; p++) {
                int cB = kk * 2 + bSel;
                uint32_t boff = (uint32_t)(Bn0 + p * 16) * 128u + (uint32_t)((cB ^ Bn7) << 4);
                ldsm4(&bh[p * 4], sB + boff);
            }
            #pragma unroll
            for (int t = 0; t < 2; t++) {
                int cA = kk * 2 + aSel;
                uint32_t aoff = (uint32_t)(Ar0 + t * 16) * 128u + (uint32_t)((cA ^ Ar7) << 4);
                uint32_t ah[4];
                ldsm4(ah, sA + aoff);
                #pragma unroll
                for (int n = 0; n < 4; n++)
                    mma16816(&acc[(t * 4 + n) * 4], ah, &bh[(n >> 1) * 4 + (n & 1) * 2]);
            }
        }
    }
    #undef LOAD_CHUNK

    const int gid = lane >> 2, qid = lane & 3;
    const float* sbias = (const float*)(smem + SM_BIAS);
    const float* sbc   = (const float*)(smem + SM_BC);
    const float* scnt  = (const float*)(smem + SM_CNT);

    #pragma unroll
    for (int t = 0; t < 2; t++) {
        #pragma unroll
        for (int n = 0; n < 4; n++) {
            float* a4 = &acc[(t * 4 + n) * 4];
            int rl = wm + t * 16 + gid;
            int cl = wn + n * 8 + qid * 2;
            size_t Rg = (size_t)tileM * 128 + rl;
            int C  = tileN * 64 + cl;
            if (MODE == 3) {
                float b0 = sbias[cl], b1 = sbias[cl + 1];
                float bc0 = sbc[cl], bc1 = sbc[cl + 1];
                float cf0 = scnt[rl], cf1 = scnt[rl + 8];
                float s00 = a4[0] + b0 + cf0 * bc0, s01 = a4[1] + b1 + cf0 * bc1;
                float s10 = a4[2] + b0 + cf1 * bc0, s11 = a4[3] + b1 + cf1 * bc1;
                __half2 y00 = *(const __half2*)&d_Yacc[Rg * DD + C];
                __half2 y01 = *(const __half2*)&d_Yacc[(Rg + 8) * DD + C];
                __half2 y10 = *(const __half2*)&d_Yacc[((size_t)N_REC + Rg) * DD + C];
                __half2 y11 = *(const __half2*)&d_Yacc[((size_t)N_REC + Rg + 8) * DD + C];
                *(__half2*)&d_Amid[Rg * DD + C] = __floats2half2_rn(
                    gelu_mufu(s00 + __low2float(y00)), gelu_mufu(s01 + __high2float(y00)));
                *(__half2*)&d_Amid[(Rg + 8) * DD + C] = __floats2half2_rn(
                    gelu_mufu(s10 + __low2float(y01)), gelu_mufu(s11 + __high2float(y01)));
                *(__half2*)&d_Amid[((size_t)N_REC + Rg) * DD + C] = __floats2half2_rn(
                    gelu_mufu(s00 + __low2float(y10)), gelu_mufu(s01 + __high2float(y10)));
                *(__half2*)&d_Amid[((size_t)N_REC + Rg + 8) * DD + C] = __floats2half2_rn(
                    gelu_mufu(s10 + __low2float(y11)), gelu_mufu(s11 + __high2float(y11)));
            } else {
                float b0 = sbias[cl], b1 = sbias[cl + 1];
                *(float2*)&outp[Rg * DD + C] = make_float2(a4[0] + b0, a4[1] + b1);
                *(float2*)&outp[(Rg + 8) * DD + C] = make_float2(a4[2] + b0, a4[3] + b1);
            }
        }
    }
}

// ---------------- launch ----------------
extern "C" void kernel_launch(void* const* d_in, const int* in_sizes, int n_in,
                              void* d_out, int out_size) {
    const float* x         = (const float*)d_in[0];
    const float* edge_attr = (const float*)d_in[1];
    const int*   idx_send  = (const int*)d_in[2];
    const int*   idx_rec   = (const int*)d_in[3];
    const float* We1       = (const float*)d_in[4];
    const float* be1       = (const float*)d_in[5];
    const float* We2       = (const float*)d_in[6];
    const float* be2       = (const float*)d_in[7];
    const float* Wl1       = (const float*)d_in[8];
    const float* bl1       = (const float*)d_in[9];
    const float* Wl2       = (const float*)d_in[10];
    const float* bl2       = (const float*)d_in[11];
    float* out = (float*)d_out;

    static bool attr_done = false;
    if (!attr_done) {
        cudaFuncSetAttribute(gemm_y, cudaFuncAttributeMaxDynamicSharedMemorySize, SMEM_Y_TOTAL);
        cudaFuncSetAttribute(gemm_hmma<3>, cudaFuncAttributeMaxDynamicSharedMemorySize, SMEM_TOTAL);
        cudaFuncSetAttribute(gemm_hmma<0>, cudaFuncAttributeMaxDynamicSharedMemorySize, SMEM_TOTAL);
        attr_done = true;
    }

    prep_all<<<1025 + (NE + 255) / 256, 256>>>(Wl1, We2, be2, Wl2, idx_rec);
    gemm_y<<<dim3(2, NROWX / 64), 256, SMEM_Y_TOTAL>>>(x);                      // Y (interleaved)
    edge_kernel<<<N_REC / 4, 256>>>(edge_attr, idx_send, We1, be1);
    gemm_hmma<3><<<dim3(4, N_REC / 128), 256, SMEM_TOTAL>>>(bl1, nullptr);      // H -> gelu -> Amid
    gemm_hmma<0><<<dim3(4, MTOT / 128), 256, SMEM_TOTAL>>>(bl2, out);           // out
}